// round 6
// baseline (speedup 1.0000x reference)
#include <cuda_runtime.h>
#include <cuda_fp16.h>
#include <cstdint>
#include <cstddef>

#define NN 4096
#define CC 128
#define BB 4
#define NEGV (-9e15f)

typedef unsigned long long ull;

// ---------------- scratch (device globals: no allocation allowed) -----------
__device__ float  g_h[(size_t)BB * CC * NN];                 // 8 MB
__device__ float  g_y[(size_t)BB * CC * NN];                 // 8 MB
__device__ __half g_qh[(size_t)BB * 32 * NN];                // 1 MB q hi [b][o][n]
__device__ __half g_ql[(size_t)BB * 32 * NN];                // 1 MB q lo
__device__ __half g_qth[(size_t)BB * NN * 32];               // 1 MB q hi transposed [b][n][o]
__device__ __half g_qtl[(size_t)BB * NN * 32];               // 1 MB q lo transposed
__device__ __half g_xvh[(size_t)BB * CC * NN];               // 4 MB value proj fp16 (pre-scaled by rowinv)
__device__ float  g_xr[(size_t)BB * CC * NN];                // 8 MB
__device__ __half g_u[(size_t)BB * NN * NN];                 // 128 MB unnormalized exp fp16
__device__ float  g_rowmaxp[(size_t)2 * BB * NN];            // row-max partials (m-split 2)
__device__ float  g_rowpart[(size_t)32 * BB * NN];           // row-sum partials (per m-tile)
__device__ float  g_rowinv[(size_t)BB * NN];                 // 1/rowsum
__device__ float  g_colpart[(size_t)8 * BB * NN];
__device__ float  g_colinv[(size_t)BB * NN];
__device__ float  g_scale[CC];
__device__ float  g_shift[CC];
__device__ float  g_bnp1[8][CC];
__device__ float  g_bnp2[8][CC];

// ---------------- helpers ----------------------------------------------------
__device__ __forceinline__ float warp_red_sum(float v) {
#pragma unroll
    for (int o = 16; o > 0; o >>= 1) v += __shfl_xor_sync(0xffffffffu, v, o);
    return v;
}

__device__ __forceinline__ void fma2(ull& acc, ull a, ull b) {
    asm("fma.rn.f32x2 %0, %1, %2, %0;" : "+l"(acc) : "l"(a), "l"(b));
}
__device__ __forceinline__ ull pack2(float v) {
    ull r;
    unsigned u = __float_as_uint(v);
    asm("mov.b64 %0, {%1, %1};" : "=l"(r) : "r"(u));
    return r;
}
__device__ __forceinline__ float2 unpack2(ull v) {
    unsigned lo, hi;
    asm("mov.b64 {%0, %1}, %2;" : "=r"(lo), "=r"(hi) : "l"(v));
    return make_float2(__uint_as_float(lo), __uint_as_float(hi));
}

__device__ __forceinline__ void fma44(float acc[4][4], float4 w, float4 x) {
    acc[0][0] += w.x * x.x; acc[0][1] += w.x * x.y; acc[0][2] += w.x * x.z; acc[0][3] += w.x * x.w;
    acc[1][0] += w.y * x.x; acc[1][1] += w.y * x.y; acc[1][2] += w.y * x.z; acc[1][3] += w.y * x.w;
    acc[2][0] += w.z * x.x; acc[2][1] += w.z * x.y; acc[2][2] += w.z * x.z; acc[2][3] += w.z * x.w;
    acc[3][0] += w.w * x.x; acc[3][1] += w.w * x.y; acc[3][2] += w.w * x.z; acc[3][3] += w.w * x.w;
}

// 8x8 (8 rows x 4 pairs) FMA2 micro-step
__device__ __forceinline__ void microstep_8x8(
    ull acc[8][4], const float* __restrict__ rowS, const double* __restrict__ pairS,
    int tc, int tp)
{
    float4 xa = *(const float4*)&rowS[tc * 8];
    float4 xb = *(const float4*)&rowS[tc * 8 + 4];
    ull xc[8];
    xc[0] = pack2(xa.x); xc[1] = pack2(xa.y); xc[2] = pack2(xa.z); xc[3] = pack2(xa.w);
    xc[4] = pack2(xb.x); xc[5] = pack2(xb.y); xc[6] = pack2(xb.z); xc[7] = pack2(xb.w);
    ull af[4];
#pragma unroll
    for (int j = 0; j < 4; j++) af[j] = *(const ull*)&pairS[tp + 16 * j];
#pragma unroll
    for (int i = 0; i < 8; i++)
#pragma unroll
        for (int j = 0; j < 4; j++) fma2(acc[i][j], xc[i], af[j]);
}

// ---------------- HMMA helpers -------------------------------------------------
__device__ __forceinline__ void ldsm_x4(unsigned& r0, unsigned& r1, unsigned& r2, unsigned& r3,
                                        const void* p) {
    unsigned addr = (unsigned)__cvta_generic_to_shared(p);
    asm volatile("ldmatrix.sync.aligned.m8n8.x4.shared.b16 {%0,%1,%2,%3}, [%4];"
        : "=r"(r0), "=r"(r1), "=r"(r2), "=r"(r3) : "r"(addr));
}
__device__ __forceinline__ void ldsm_x4_t(unsigned& r0, unsigned& r1, unsigned& r2, unsigned& r3,
                                          const void* p) {
    unsigned addr = (unsigned)__cvta_generic_to_shared(p);
    asm volatile("ldmatrix.sync.aligned.m8n8.x4.trans.shared.b16 {%0,%1,%2,%3}, [%4];"
        : "=r"(r0), "=r"(r1), "=r"(r2), "=r"(r3) : "r"(addr));
}
__device__ __forceinline__ void mma16816(float d[4], const unsigned a[4], const unsigned b[2]) {
    asm volatile("mma.sync.aligned.m16n8k16.row.col.f32.f16.f16.f32 "
        "{%0,%1,%2,%3}, {%4,%5,%6,%7}, {%8,%9}, {%0,%1,%2,%3};"
        : "+f"(d[0]), "+f"(d[1]), "+f"(d[2]), "+f"(d[3])
        : "r"(a[0]), "r"(a[1]), "r"(a[2]), "r"(a[3]), "r"(b[0]), "r"(b[1]));
}

// ---------------- gemm_qk: q = Wqk (32xC) * X; writes fp16 hi/lo + transposed --
__global__ __launch_bounds__(256) void gemm_qk(
    const float* __restrict__ W, const float* __restrict__ X,
    __half* __restrict__ QH, __half* __restrict__ QL,
    __half* __restrict__ QTH, __half* __restrict__ QTL)
{
    __shared__ float Ws[CC][32];
    __shared__ float Xs[64][128];

    const int b  = blockIdx.z;
    const int n0 = blockIdx.x * 128;
    const int tid = threadIdx.x;

    for (int idx = tid; idx < 32 * CC; idx += 256) {
        int o = idx / CC, c = idx % CC;
        Ws[c][o] = W[(size_t)o * CC + c];
    }

    const float* x1 = X + (size_t)b * CC * NN;

    float acc[4][4] = {};
    const int to = tid / 32, tn = tid % 32;

    for (int c0 = 0; c0 < CC; c0 += 64) {
        __syncthreads();
        for (int idx = tid; idx < 64 * 128; idx += 256) {
            int c = idx / 128, n = idx % 128;
            Xs[c][n] = x1[(size_t)(c0 + c) * NN + n0 + n];
        }
        __syncthreads();
#pragma unroll 8
        for (int c = 0; c < 64; c++) {
            float4 w = *(const float4*)&Ws[c0 + c][to * 4];
            float4 x = *(const float4*)&Xs[c][tn * 4];
            fma44(acc, w, x);
        }
    }

    __half h[4][4], l[4][4];
#pragma unroll
    for (int i = 0; i < 4; i++)
#pragma unroll
        for (int j = 0; j < 4; j++) {
            h[i][j] = __float2half_rn(acc[i][j]);
            l[i][j] = __float2half_rn(acc[i][j] - __half2float(h[i][j]));
        }

#pragma unroll
    for (int i = 0; i < 4; i++) {
        int o = to * 4 + i;
        size_t off = ((size_t)b * 32 + o) * NN + n0 + tn * 4;
        __half2 h0 = __halves2half2(h[i][0], h[i][1]);
        __half2 h1 = __halves2half2(h[i][2], h[i][3]);
        uint2 pk; pk.x = *(unsigned*)&h0; pk.y = *(unsigned*)&h1;
        *(uint2*)&QH[off] = pk;
        __half2 l0 = __halves2half2(l[i][0], l[i][1]);
        __half2 l1 = __halves2half2(l[i][2], l[i][3]);
        uint2 pl; pl.x = *(unsigned*)&l0; pl.y = *(unsigned*)&l1;
        *(uint2*)&QL[off] = pl;
    }
#pragma unroll
    for (int j = 0; j < 4; j++) {
        int n = n0 + tn * 4 + j;
        size_t off = ((size_t)b * NN + n) * 32 + to * 4;
        __half2 h0 = __halves2half2(h[0][j], h[1][j]);
        __half2 h1 = __halves2half2(h[2][j], h[3][j]);
        uint2 pk; pk.x = *(unsigned*)&h0; pk.y = *(unsigned*)&h1;
        *(uint2*)&QTH[off] = pk;
        __half2 l0 = __halves2half2(l[0][j], l[1][j]);
        __half2 l1 = __halves2half2(l[2][j], l[3][j]);
        uint2 pl; pl.x = *(unsigned*)&l0; pl.y = *(unsigned*)&l1;
        *(uint2*)&QTL[off] = pl;
    }
}

// ---------------- gemm128: Y[b,o,n] = sum_c W[o,c]*(X1-X2)[b,c,n] + bias ------
// fp16 output path optionally scales by rowinv[n].
__global__ __launch_bounds__(256, 2) void gemm128(
    const float* __restrict__ W, const float* __restrict__ X1,
    const float* __restrict__ X2, const float* __restrict__ bias,
    float* __restrict__ Y, __half* __restrict__ Yh,
    const float* __restrict__ rowinv)
{
    __shared__ float  Ws[32][132];
    __shared__ double Xd[32][66];

    const int b  = blockIdx.y;
    const int n0 = blockIdx.x * 128;
    const int tid = threadIdx.x;
    const int tp = tid & 15;
    const int tc = tid >> 4;

    const float* x1 = X1 + (size_t)b * CC * NN;
    const float* x2 = X2 ? X2 + (size_t)b * CC * NN : nullptr;

    ull acc[8][4];
#pragma unroll
    for (int i = 0; i < 8; i++)
#pragma unroll
        for (int j = 0; j < 4; j++) acc[i][j] = 0ull;

    for (int c0 = 0; c0 < CC; c0 += 32) {
        {
            int o = tid & 127, h = tid >> 7;
            const float* wsrc = W + (size_t)o * CC + c0 + h * 16;
            float4 wv[4];
#pragma unroll
            for (int r = 0; r < 4; r++) wv[r] = *(const float4*)&wsrc[r * 4];
#pragma unroll
            for (int r = 0; r < 4; r++) {
                int cbase = h * 16 + r * 4;
                Ws[cbase + 0][o] = wv[r].x;
                Ws[cbase + 1][o] = wv[r].y;
                Ws[cbase + 2][o] = wv[r].z;
                Ws[cbase + 3][o] = wv[r].w;
            }
        }
#pragma unroll
        for (int t = 0; t < 4; t++) {
            int idx = tid + t * 256;
            int c = idx >> 5, q = idx & 31;
            float4 v = *(const float4*)&x1[(size_t)(c0 + c) * NN + n0 + q * 4];
            if (x2) {
                float4 w = *(const float4*)&x2[(size_t)(c0 + c) * NN + n0 + q * 4];
                v.x -= w.x; v.y -= w.y; v.z -= w.z; v.w -= w.w;
            }
            *(double2*)&Xd[c][q * 2] = *(const double2*)&v;
        }
        __syncthreads();
#pragma unroll
        for (int k = 0; k < 32; k++)
            microstep_8x8(acc, &Ws[k][0], &Xd[k][0], tc, tp);
        __syncthreads();
    }

#pragma unroll
    for (int i = 0; i < 8; i++) {
        int o = tc * 8 + i;
        float bi = bias ? bias[o] : 0.f;
#pragma unroll
        for (int j = 0; j < 4; j++) {
            float2 r = unpack2(acc[i][j]);
            r.x += bi; r.y += bi;
            int col = n0 + 2 * (tp + 16 * j);
            size_t off = ((size_t)b * CC + o) * NN + col;
            if (Yh) {
                if (rowinv) {
                    float2 ri = *(const float2*)&rowinv[(size_t)b * NN + col];
                    r.x *= ri.x; r.y *= ri.y;
                }
                *(__half2*)&Yh[off] = __floats2half2_rn(r.x, r.y);
            } else {
                *(float2*)&Y[off] = r;
            }
        }
    }
}

// ---------------- pass 1: masked row-max of energy (hi-only HMMA recompute) ----
// block tile 64n, sweeps half the m range (m-split 2). 8 warps (2n x 4m).
__global__ __launch_bounds__(256, 2) void rowmax_kernel(
    const __half* __restrict__ QH, const __half* __restrict__ QTH,
    const int* __restrict__ mask)
{
    __shared__ __half Ah[64][40];
    __shared__ __half Bh[32][136];
    __shared__ int   cms[128];
    __shared__ float rmaxs[64][4];

    const int b  = blockIdx.z;
    const int ms = blockIdx.y;           // m-split 0/1
    const int n0 = blockIdx.x * 64;
    const int tid = threadIdx.x;
    const int wid = tid >> 5, lane = tid & 31;
    const int wn = wid & 1, wm = wid >> 1;

    {
        int r = tid >> 2, s = tid & 3;
        *(uint4*)&Ah[r][s * 8] = *(const uint4*)&QTH[((size_t)b * NN + n0 + r) * 32 + s * 8];
    }
    __syncthreads();

    const int lrow = (lane & 7) + ((lane >> 3) & 1) * 8;
    const int lsel = lane >> 4;
    const int g = lane >> 3;
    const int r0l = lane >> 2, c0l = (lane & 3) * 2;

    unsigned ah[2][2][4];   // [kk][ci]
#pragma unroll
    for (int kk = 0; kk < 2; kk++)
#pragma unroll
        for (int ci = 0; ci < 2; ci++)
            ldsm_x4(ah[kk][ci][0], ah[kk][ci][1], ah[kk][ci][2], ah[kk][ci][3],
                    &Ah[wn * 32 + ci * 16 + lrow][kk * 16 + lsel * 8]);

    float vmax[2][2];       // [ci][half]
    vmax[0][0] = NEGV; vmax[0][1] = NEGV; vmax[1][0] = NEGV; vmax[1][1] = NEGV;

    for (int chunk = 0; chunk < 16; chunk++) {
        const int m0 = ms * 2048 + chunk * 128;
        __syncthreads();
#pragma unroll
        for (int u = 0; u < 2; u++) {
            int idx = tid + u * 256;
            int r = idx >> 4, s = idx & 15;
            *(uint4*)&Bh[r][s * 8] = *(const uint4*)&QH[((size_t)b * 32 + r) * NN + m0 + s * 8];
        }
        if (tid < 128) cms[tid] = mask[(size_t)b * NN + m0 + tid];
        __syncthreads();

        float acc[2][4][4];
#pragma unroll
        for (int i = 0; i < 2; i++)
#pragma unroll
            for (int j = 0; j < 4; j++)
#pragma unroll
                for (int k = 0; k < 4; k++) acc[i][j][k] = 0.f;

#pragma unroll
        for (int kk = 0; kk < 2; kk++) {
            unsigned bh[4][2];
#pragma unroll
            for (int h = 0; h < 2; h++) {
                unsigned t0, t1, t2, t3;
                ldsm_x4_t(t0, t1, t2, t3,
                          &Bh[kk * 16 + (g & 1) * 8 + (lane & 7)][wm * 32 + h * 16 + (g >> 1) * 8]);
                bh[h * 2 + 0][0] = t0; bh[h * 2 + 0][1] = t1;
                bh[h * 2 + 1][0] = t2; bh[h * 2 + 1][1] = t3;
            }
#pragma unroll
            for (int ci = 0; ci < 2; ci++)
#pragma unroll
                for (int nf = 0; nf < 4; nf++)
                    mma16816(acc[ci][nf], ah[kk][ci], bh[nf]);
        }

#pragma unroll
        for (int ci = 0; ci < 2; ci++)
#pragma unroll
            for (int nf = 0; nf < 4; nf++) {
                int mm = wm * 32 + nf * 8 + c0l;
                float v0, v1;
                v0 = cms[mm]     ? acc[ci][nf][0] : NEGV;
                v1 = cms[mm + 1] ? acc[ci][nf][1] : NEGV;
                vmax[ci][0] = fmaxf(vmax[ci][0], fmaxf(v0, v1));
                v0 = cms[mm]     ? acc[ci][nf][2] : NEGV;
                v1 = cms[mm + 1] ? acc[ci][nf][3] : NEGV;
                vmax[ci][1] = fmaxf(vmax[ci][1], fmaxf(v0, v1));
            }
    }

#pragma unroll
    for (int ci = 0; ci < 2; ci++)
#pragma unroll
        for (int h = 0; h < 2; h++) {
            float v = vmax[ci][h];
            v = fmaxf(v, __shfl_xor_sync(0xffffffffu, v, 1));
            v = fmaxf(v, __shfl_xor_sync(0xffffffffu, v, 2));
            vmax[ci][h] = v;
        }
    if ((lane & 3) == 0) {
#pragma unroll
        for (int ci = 0; ci < 2; ci++)
#pragma unroll
            for (int h = 0; h < 2; h++)
                rmaxs[wn * 32 + ci * 16 + h * 8 + r0l][wm] = vmax[ci][h];
    }
    __syncthreads();
    if (tid < 64) {
        float v = fmaxf(fmaxf(rmaxs[tid][0], rmaxs[tid][1]),
                        fmaxf(rmaxs[tid][2], rmaxs[tid][3]));
        if (mask[(size_t)b * NN + n0 + tid] == 0) v = NEGV;
        g_rowmaxp[((size_t)ms * BB + b) * NN + n0 + tid] = v;
    }
}

// ---------------- pass 2: recompute energy (hi/lo), write u=exp(v-max) fp16 ----
// block tile 64n x 128m; also emits per-(m-tile) row-sum partials (deterministic).
__global__ __launch_bounds__(256, 2) void exp_kernel(
    const __half* __restrict__ QH, const __half* __restrict__ QL,
    const __half* __restrict__ QTH, const __half* __restrict__ QTL,
    const int* __restrict__ mask, __half* __restrict__ U)
{
    __shared__ __half Ah[64][40];
    __shared__ __half Al[64][40];
    __shared__ __half Bh[32][136];
    __shared__ __half Bl[32][136];
    __shared__ int   cms[128];
    __shared__ float rsums[64][4];

    const int b  = blockIdx.z;
    const int n0 = blockIdx.y * 64;
    const int m0 = blockIdx.x * 128;
    const int mt = blockIdx.x;
    const int tid = threadIdx.x;
    const int wid = tid >> 5, lane = tid & 31;
    const int wn = wid & 1, wm = wid >> 1;

    {
        int r = tid >> 2, s = tid & 3;
        size_t off = ((size_t)b * NN + n0 + r) * 32 + s * 8;
        *(uint4*)&Ah[r][s * 8] = *(const uint4*)&QTH[off];
        *(uint4*)&Al[r][s * 8] = *(const uint4*)&QTL[off];
    }
#pragma unroll
    for (int u = 0; u < 2; u++) {
        int idx = tid + u * 256;
        int r = idx >> 4, s = idx & 15;
        size_t off = ((size_t)b * 32 + r) * NN + m0 + s * 8;
        *(uint4*)&Bh[r][s * 8] = *(const uint4*)&QH[off];
        *(uint4*)&Bl[r][s * 8] = *(const uint4*)&QL[off];
    }
    if (tid < 128) cms[tid] = mask[(size_t)b * NN + m0 + tid];
    __syncthreads();

    float acc[2][4][4];
#pragma unroll
    for (int i = 0; i < 2; i++)
#pragma unroll
        for (int j = 0; j < 4; j++)
#pragma unroll
            for (int k = 0; k < 4; k++) acc[i][j][k] = 0.f;

    const int lrow = (lane & 7) + ((lane >> 3) & 1) * 8;
    const int lsel = lane >> 4;
    const int g = lane >> 3;
    const int r0l = lane >> 2, c0l = (lane & 3) * 2;

#pragma unroll
    for (int kk = 0; kk < 2; kk++) {
        unsigned ah[2][4], al[2][4];
#pragma unroll
        for (int ci = 0; ci < 2; ci++) {
            ldsm_x4(ah[ci][0], ah[ci][1], ah[ci][2], ah[ci][3],
                    &Ah[wn * 32 + ci * 16 + lrow][kk * 16 + lsel * 8]);
            ldsm_x4(al[ci][0], al[ci][1], al[ci][2], al[ci][3],
                    &Al[wn * 32 + ci * 16 + lrow][kk * 16 + lsel * 8]);
        }
        unsigned bh[4][2], bl[4][2];
#pragma unroll
        for (int h = 0; h < 2; h++) {
            unsigned t0, t1, t2, t3;
            ldsm_x4_t(t0, t1, t2, t3,
                      &Bh[kk * 16 + (g & 1) * 8 + (lane & 7)][wm * 32 + h * 16 + (g >> 1) * 8]);
            bh[h * 2 + 0][0] = t0; bh[h * 2 + 0][1] = t1;
            bh[h * 2 + 1][0] = t2; bh[h * 2 + 1][1] = t3;
            ldsm_x4_t(t0, t1, t2, t3,
                      &Bl[kk * 16 + (g & 1) * 8 + (lane & 7)][wm * 32 + h * 16 + (g >> 1) * 8]);
            bl[h * 2 + 0][0] = t0; bl[h * 2 + 0][1] = t1;
            bl[h * 2 + 1][0] = t2; bl[h * 2 + 1][1] = t3;
        }
#pragma unroll
        for (int ci = 0; ci < 2; ci++)
#pragma unroll
            for (int nf = 0; nf < 4; nf++) {
                mma16816(acc[ci][nf], ah[ci], bh[nf]);
                mma16816(acc[ci][nf], ah[ci], bl[nf]);
                mma16816(acc[ci][nf], al[ci], bh[nf]);
            }
    }

    // per-lane row info: rows n0 + wn*32 + ci*16 + h*8 + r0l
    int   rmv[2][2];
    float mxv[2][2];
#pragma unroll
    for (int ci = 0; ci < 2; ci++)
#pragma unroll
        for (int h = 0; h < 2; h++) {
            int n = n0 + wn * 32 + ci * 16 + h * 8 + r0l;
            rmv[ci][h] = mask[(size_t)b * NN + n];
            mxv[ci][h] = fmaxf(g_rowmaxp[(size_t)b * NN + n],
                               g_rowmaxp[((size_t)BB + b) * NN + n]);
        }

    float rsum[2][2] = {{0.f, 0.f}, {0.f, 0.f}};
#pragma unroll
    for (int ci = 0; ci < 2; ci++)
#pragma unroll
        for (int nf = 0; nf < 4; nf++) {
            int mm = wm * 32 + nf * 8 + c0l;
            int cm0 = cms[mm], cm1 = cms[mm + 1];
#pragma unroll
            for (int h = 0; h < 2; h++) {
                float e0 = acc[ci][nf][h * 2 + 0];
                float e1 = acc[ci][nf][h * 2 + 1];
                float v0 = (rmv[ci][h] && cm0) ? e0 : NEGV;
                float v1 = (rmv[ci][h] && cm1) ? e1 : NEGV;
                float u0 = __expf(v0 - mxv[ci][h]);
                float u1 = __expf(v1 - mxv[ci][h]);
                int n = n0 + wn * 32 + ci * 16 + h * 8 + r0l;
                *(__half2*)&U[((size_t)b * NN + n) * NN + m0 + mm] = __floats2half2_rn(u0, u1);
                rsum[ci][h] += u0 + u1;
            }
        }

#pragma unroll
    for (int ci = 0; ci < 2; ci++)
#pragma unroll
        for (int h = 0; h < 2; h++) {
            float v = rsum[ci][h];
            v += __shfl_xor_sync(0xffffffffu, v, 1);
            v += __shfl_xor_sync(0xffffffffu, v, 2);
            rsum[ci][h] = v;
        }
    if ((lane & 3) == 0) {
#pragma unroll
        for (int ci = 0; ci < 2; ci++)
#pragma unroll
            for (int h = 0; h < 2; h++)
                rsums[wn * 32 + ci * 16 + h * 8 + r0l][wm] = rsum[ci][h];
    }
    __syncthreads();
    if (tid < 64) {
        float s = (rsums[tid][0] + rsums[tid][1]) + (rsums[tid][2] + rsums[tid][3]);
        g_rowpart[((size_t)mt * BB + b) * NN + n0 + tid] = s;
    }
}

// ---------------- rowsum finalize: rowinv = 1/sum(partials) --------------------
__global__ __launch_bounds__(256) void rowfin_kernel()
{
    const int b = blockIdx.y;
    const int n = blockIdx.x * 256 + threadIdx.x;
    float s = 0.f;
#pragma unroll
    for (int t = 0; t < 32; t++)
        s += g_rowpart[((size_t)t * BB + b) * NN + n];
    g_rowinv[(size_t)b * NN + n] = 1.f / s;
}

// ---------------- column-sum of row-normalized u ------------------------------
__global__ __launch_bounds__(256) void colpart_kernel(const __half* __restrict__ U)
{
    const int b = blockIdx.z;
    const int split = blockIdx.y;
    const int m2 = blockIdx.x * 256 + threadIdx.x;
    const __half2* a = (const __half2*)(U + (size_t)b * NN * NN) + m2;
    const float* ri = g_rowinv + (size_t)b * NN;
    const int nbeg = split * 512;
    float2 s0 = make_float2(0.f, 0.f), s1 = make_float2(0.f, 0.f);
#pragma unroll 4
    for (int n = nbeg; n < nbeg + 512; n += 2) {
        float2 f0 = __half22float2(a[(size_t)(n + 0) * (NN / 2)]);
        float2 f1 = __half22float2(a[(size_t)(n + 1) * (NN / 2)]);
        float r0 = ri[n], r1 = ri[n + 1];
        s0.x += f0.x * r0; s0.y += f0.y * r0;
        s1.x += f1.x * r1; s1.y += f1.y * r1;
    }
    float2 r = make_float2(s0.x + s1.x, s0.y + s1.y);
    *(float2*)&g_colpart[((size_t)split * BB + b) * NN + 2 * m2] = r;
}

__global__ __launch_bounds__(256) void colfin_kernel()
{
    const int b = blockIdx.y;
    const int m = blockIdx.x * 256 + threadIdx.x;
    float s = 0.f;
#pragma unroll
    for (int split = 0; split < 8; split++)
        s += g_colpart[((size_t)split * BB + b) * NN + m];
    g_colinv[(size_t)b * NN + m] = 1.f / (1e-9f + s);
}

// ---------------- attn apply via HMMA: XR = (XV' @ U) * colinv -----------------
// 256 threads = 8 warps (4c x 2m), block tile 128c x 64m.
__global__ __launch_bounds__(256, 2) void apply_hmma(
    const __half* __restrict__ XVH, const __half* __restrict__ U,
    float* __restrict__ XR)
{
    __shared__ __half XVs[128][72];
    __shared__ __half As[64][72];

    const int b  = blockIdx.y;
    const int m0 = blockIdx.x * 64;
    const int tid = threadIdx.x;
    const int wid = tid >> 5, lane = tid & 31;
    const int wc = wid & 3, wm = wid >> 2;

    const __half* xv = XVH + (size_t)b * CC * NN;
    const __half* at = U + (size_t)b * NN * NN;

    float acc[2][4][4];
#pragma unroll
    for (int i = 0; i < 2; i++)
#pragma unroll
        for (int j = 0; j < 4; j++)
#pragma unroll
            for (int k = 0; k < 4; k++) acc[i][j][k] = 0.f;

    const int lrow = (lane & 7) + ((lane >> 3) & 1) * 8;
    const int lsel = lane >> 4;
    const int g = lane >> 3;

    for (int k0 = 0; k0 < NN; k0 += 64) {
#pragma unroll
        for (int u = 0; u < 4; u++) {
            int idx = tid + u * 256;
            int r = idx >> 3, s = idx & 7;
            *(uint4*)&XVs[r][s * 8] = *(const uint4*)&xv[(size_t)r * NN + k0 + s * 8];
        }
#pragma unroll
        for (int u = 0; u < 2; u++) {
            int idx = tid + u * 256;
            int r = idx >> 3, s = idx & 7;
            *(uint4*)&As[r][s * 8] = *(const uint4*)&at[(size_t)(k0 + r) * NN + m0 + s * 8];
        }
        __syncthreads();

#pragma unroll
        for (int kk = 0; kk < 4; kk++) {
            unsigned a[2][4];
#pragma unroll
            for (int ci = 0; ci < 2; ci++)
                ldsm_x4(a[ci][0], a[ci][1], a[ci][2], a[ci][3],
                        &XVs[wc * 32 + ci * 16 + lrow][kk * 16 + lsel * 8]);
            unsigned bf[4][2];
#pragma unroll
            for (int h = 0; h < 2; h++) {
                unsigned t0, t1, t2, t3;
                ldsm_x4_t(t0, t1, t2, t3,
                          &As[kk * 16 + (g & 1) * 8 + (lane & 7)][wm * 32 + h * 16 + (g >> 1) * 8]);
                bf[h * 2 + 0][0] = t0; bf[h * 2 + 0][1] = t1;
                bf[h * 2 + 1][0] = t2; bf[h * 2 + 1][1] = t3;
            }
#pragma unroll
            for (int ci = 0; ci < 2; ci++)
#pragma unroll
                for (int nf = 0; nf < 4; nf++)
                    mma16816(acc[ci][nf], a[ci], bf[nf]);
        }
        __syncthreads();
    }

    const float* cinv = g_colinv + (size_t)b * NN + m0;
    const int r0l = lane >> 2, c0l = (lane & 3) * 2;
#pragma unroll
    for (int ci = 0; ci < 2; ci++) {
#pragma unroll
        for (int nf = 0; nf < 4; nf++) {
            int c = wc * 32 + ci * 16 + r0l;
            int mm = wm * 32 + nf * 8 + c0l;
            float2 cv = *(const float2*)&cinv[mm];
            float2 lo = make_float2(acc[ci][nf][0] * cv.x, acc[ci][nf][1] * cv.y);
            *(float2*)&XR[((size_t)b * CC + c) * NN + m0 + mm] = lo;
            float2 hi = make_float2(acc[ci][nf][2] * cv.x, acc[ci][nf][3] * cv.y);
            *(float2*)&XR[((size_t)b * CC + c + 8) * NN + m0 + mm] = hi;
        }
    }
}

// ---------------- BN stats: 8-way partials + finalize ---------------------------
__global__ __launch_bounds__(256) void bn_part_kernel(const float* __restrict__ Y)
{
    const int c = blockIdx.x;
    const int s = blockIdx.y;
    const int b = s >> 1;
    const int n0 = (s & 1) * 2048;
    const float* p = Y + ((size_t)b * CC + c) * NN + n0;
    const int tid = threadIdx.x;
    float sum = 0.f, sq = 0.f;
#pragma unroll
    for (int i = 0; i < 8; i++) {
        float v = p[tid + i * 256];
        sum += v; sq += v * v;
    }
    sum = warp_red_sum(sum); sq = warp_red_sum(sq);
    __shared__ float r1[8], r2[8];
    if ((tid & 31) == 0) { r1[tid >> 5] = sum; r2[tid >> 5] = sq; }
    __syncthreads();
    if (tid == 0) {
        float ts = 0.f, t2 = 0.f;
#pragma unroll
        for (int i = 0; i < 8; i++) { ts += r1[i]; t2 += r2[i]; }
        g_bnp1[s][c] = ts;
        g_bnp2[s][c] = t2;
    }
}

__global__ void bn_finalize_kernel(const float* __restrict__ gam, const float* __restrict__ bet)
{
    const int c = threadIdx.x;
    float ts = 0.f, t2 = 0.f;
#pragma unroll
    for (int s = 0; s < 8; s++) { ts += g_bnp1[s][c]; t2 += g_bnp2[s][c]; }
    const float invN = 1.f / (float)(BB * NN);
    float mean = ts * invN;
    float var  = t2 * invN - mean * mean;
    float sc = gam[c] * rsqrtf(var + 1e-5f);
    g_scale[c] = sc;
    g_shift[c] = bet[c] - mean * sc;
}

// ---------------- BN apply (+relu) [+residual into h and output slab] -----------
__global__ __launch_bounds__(256) void bn_apply_kernel(
    const float* __restrict__ Y, float* __restrict__ H,
    float* __restrict__ OUT, int layer)
{
    size_t f = ((size_t)blockIdx.x * 256 + threadIdx.x) * 4;
    int n = (int)(f % NN);
    int c = (int)((f / NN) % CC);
    int b = (int)(f / ((size_t)NN * CC));
    float sc = g_scale[c], sh = g_shift[c];
    float4 y = *(const float4*)&Y[f];
    float4 r;
    r.x = fmaxf(fmaf(y.x, sc, sh), 0.f);
    r.y = fmaxf(fmaf(y.y, sc, sh), 0.f);
    r.z = fmaxf(fmaf(y.z, sc, sh), 0.f);
    r.w = fmaxf(fmaf(y.w, sc, sh), 0.f);
    if (OUT) {
        float4 h = *(const float4*)&H[f];
        r.x += h.x; r.y += h.y; r.z += h.z; r.w += h.w;
        *(float4*)&H[f] = r;
        *(float4*)&OUT[(((size_t)b * 4 * CC) + (size_t)layer * CC + c) * NN + n] = r;
    } else {
        *(float4*)&H[f] = r;
    }
}

// ---------------- launch ---------------------------------------------------------
extern "C" void kernel_launch(void* const* d_in, const int* in_sizes, int n_in,
                              void* d_out, int out_size)
{
    const float* x    = (const float*)d_in[0];
    const int*   mask = (const int*)  d_in[1];
    const float* w1   = (const float*)d_in[2];
    const float* g1   = (const float*)d_in[3];
    const float* b1   = (const float*)d_in[4];
    const float* w2   = (const float*)d_in[5];
    const float* g2   = (const float*)d_in[6];
    const float* b2   = (const float*)d_in[7];
    const float* wqk  = (const float*)d_in[8];
    const float* wv   = (const float*)d_in[9];
    const float* bv   = (const float*)d_in[10];
    const float* wt   = (const float*)d_in[11];
    const float* bt   = (const float*)d_in[12];
    const float* sg   = (const float*)d_in[13];
    const float* sb   = (const float*)d_in[14];
    float* out = (float*)d_out;

    float *p_h, *p_y, *p_xr, *p_rowinv;
    __half *p_xvh, *p_u, *p_qh, *p_ql, *p_qth, *p_qtl;
    cudaGetSymbolAddress((void**)&p_h,      g_h);
    cudaGetSymbolAddress((void**)&p_y,      g_y);
    cudaGetSymbolAddress((void**)&p_xvh,    g_xvh);
    cudaGetSymbolAddress((void**)&p_xr,     g_xr);
    cudaGetSymbolAddress((void**)&p_u,      g_u);
    cudaGetSymbolAddress((void**)&p_qh,     g_qh);
    cudaGetSymbolAddress((void**)&p_ql,     g_ql);
    cudaGetSymbolAddress((void**)&p_qth,    g_qth);
    cudaGetSymbolAddress((void**)&p_qtl,    g_qtl);
    cudaGetSymbolAddress((void**)&p_rowinv, g_rowinv);

    const dim3 blk256(256);
    const dim3 grid_g128(NN / 128, BB);
    const dim3 grid_qk(NN / 128, 1, BB);
    const dim3 grid_rm(NN / 64, 2, BB);
    const dim3 grid_ex(NN / 128, NN / 64, BB);
    const dim3 grid_rf(NN / 256, BB);
    const dim3 grid_cp(NN / 512, 8, BB);
    const dim3 grid_cf(NN / 256, BB);
    const dim3 grid_ap(NN / 64, BB);
    const dim3 grid_bp(CC, 8);
    const dim3 grid_ba((unsigned)(((size_t)BB * CC * NN / 4) / 256));

    // head: two conv+BN+relu
    gemm128<<<grid_g128, blk256>>>(w1, x, nullptr, nullptr, p_y, nullptr, nullptr);
    bn_part_kernel<<<grid_bp, blk256>>>(p_y);
    bn_finalize_kernel<<<1, CC>>>(g1, b1);
    bn_apply_kernel<<<grid_ba, blk256>>>(p_y, p_h, nullptr, 0);

    gemm128<<<grid_g128, blk256>>>(w2, p_h, nullptr, nullptr, p_y, nullptr, nullptr);
    bn_part_kernel<<<grid_bp, blk256>>>(p_y);
    bn_finalize_kernel<<<1, CC>>>(g2, b2);
    bn_apply_kernel<<<grid_ba, blk256>>>(p_y, p_h, nullptr, 0);

    // 4 offset-attention layers
    for (int i = 0; i < 4; i++) {
        gemm_qk<<<grid_qk, blk256>>>(wqk + (size_t)i * 32 * CC, p_h, p_qh, p_ql, p_qth, p_qtl);
        rowmax_kernel<<<grid_rm, blk256>>>(p_qh, p_qth, mask);
        exp_kernel<<<grid_ex, blk256>>>(p_qh, p_ql, p_qth, p_qtl, mask, p_u);
        rowfin_kernel<<<grid_rf, blk256>>>();
        gemm128<<<grid_g128, blk256>>>(wv + (size_t)i * CC * CC, p_h, nullptr, bv + (size_t)i * CC,
                                       nullptr, p_xvh, p_rowinv);
        colpart_kernel<<<grid_cp, blk256>>>(p_u);
        colfin_kernel<<<grid_cf, blk256>>>();
        apply_hmma<<<grid_ap, blk256>>>(p_xvh, p_u, p_xr);
        gemm128<<<grid_g128, blk256>>>(wt + (size_t)i * CC * CC, p_h, p_xr, bt + (size_t)i * CC,
                                       p_y, nullptr, nullptr);
        bn_part_kernel<<<grid_bp, blk256>>>(p_y);
        bn_finalize_kernel<<<1, CC>>>(sg + (size_t)i * CC, sb + (size_t)i * CC);
        bn_apply_kernel<<<grid_ba, blk256>>>(p_y, p_h, out, i);
    }
}

// round 7
// speedup vs baseline: 1.3856x; 1.3856x over previous
#include <cuda_runtime.h>
#include <cuda_fp16.h>
#include <cstdint>
#include <cstddef>

#define NN 4096
#define CC 128
#define BB 4
#define NEGV (-9e15f)

typedef unsigned long long ull;

// ---------------- scratch (device globals: no allocation allowed) -----------
__device__ float  g_h[(size_t)BB * CC * NN];                 // 8 MB
__device__ float  g_y[(size_t)BB * CC * NN];                 // 8 MB
__device__ __half g_qh[(size_t)BB * 32 * NN];                // 1 MB q hi [b][o][n]
__device__ __half g_ql[(size_t)BB * 32 * NN];                // 1 MB q lo
__device__ __half g_qth[(size_t)BB * NN * 32];               // 1 MB q hi transposed
__device__ __half g_qtl[(size_t)BB * NN * 32];               // 1 MB q lo transposed
__device__ __half g_xvh[(size_t)BB * CC * NN];               // 4 MB value proj fp16
__device__ float  g_xr[(size_t)BB * CC * NN];                // 8 MB
__device__ __half g_u[(size_t)BB * NN * NN];                 // 128 MB tile-softmaxed exp fp16
__device__ float  g_tmax[(size_t)32 * BB * NN];              // per-(m-tile) row max
__device__ float  g_tsum[(size_t)32 * BB * NN];              // per-(m-tile) row expsum
__device__ float  g_rowscale[(size_t)32 * BB * NN];          // f[t][b][n]
__device__ float  g_scale[CC];
__device__ float  g_shift[CC];
__device__ float  g_bnp1[8][CC];
__device__ float  g_bnp2[8][CC];

// ---------------- helpers ----------------------------------------------------
__device__ __forceinline__ float warp_red_sum(float v) {
#pragma unroll
    for (int o = 16; o > 0; o >>= 1) v += __shfl_xor_sync(0xffffffffu, v, o);
    return v;
}

__device__ __forceinline__ void fma2(ull& acc, ull a, ull b) {
    asm("fma.rn.f32x2 %0, %1, %2, %0;" : "+l"(acc) : "l"(a), "l"(b));
}
__device__ __forceinline__ ull pack2(float v) {
    ull r;
    unsigned u = __float_as_uint(v);
    asm("mov.b64 %0, {%1, %1};" : "=l"(r) : "r"(u));
    return r;
}
__device__ __forceinline__ float2 unpack2(ull v) {
    unsigned lo, hi;
    asm("mov.b64 {%0, %1}, %2;" : "=r"(lo), "=r"(hi) : "l"(v));
    return make_float2(__uint_as_float(lo), __uint_as_float(hi));
}

__device__ __forceinline__ void fma44(float acc[4][4], float4 w, float4 x) {
    acc[0][0] += w.x * x.x; acc[0][1] += w.x * x.y; acc[0][2] += w.x * x.z; acc[0][3] += w.x * x.w;
    acc[1][0] += w.y * x.x; acc[1][1] += w.y * x.y; acc[1][2] += w.y * x.z; acc[1][3] += w.y * x.w;
    acc[2][0] += w.z * x.x; acc[2][1] += w.z * x.y; acc[2][2] += w.z * x.z; acc[2][3] += w.z * x.w;
    acc[3][0] += w.w * x.x; acc[3][1] += w.w * x.y; acc[3][2] += w.w * x.z; acc[3][3] += w.w * x.w;
}

__device__ __forceinline__ void microstep_8x8(
    ull acc[8][4], const float* __restrict__ rowS, const double* __restrict__ pairS,
    int tc, int tp)
{
    float4 xa = *(const float4*)&rowS[tc * 8];
    float4 xb = *(const float4*)&rowS[tc * 8 + 4];
    ull xc[8];
    xc[0] = pack2(xa.x); xc[1] = pack2(xa.y); xc[2] = pack2(xa.z); xc[3] = pack2(xa.w);
    xc[4] = pack2(xb.x); xc[5] = pack2(xb.y); xc[6] = pack2(xb.z); xc[7] = pack2(xb.w);
    ull af[4];
#pragma unroll
    for (int j = 0; j < 4; j++) af[j] = *(const ull*)&pairS[tp + 16 * j];
#pragma unroll
    for (int i = 0; i < 8; i++)
#pragma unroll
        for (int j = 0; j < 4; j++) fma2(acc[i][j], xc[i], af[j]);
}

// ---------------- HMMA helpers -------------------------------------------------
__device__ __forceinline__ void ldsm_x4(unsigned& r0, unsigned& r1, unsigned& r2, unsigned& r3,
                                        const void* p) {
    unsigned addr = (unsigned)__cvta_generic_to_shared(p);
    asm volatile("ldmatrix.sync.aligned.m8n8.x4.shared.b16 {%0,%1,%2,%3}, [%4];"
        : "=r"(r0), "=r"(r1), "=r"(r2), "=r"(r3) : "r"(addr));
}
__device__ __forceinline__ void ldsm_x4_t(unsigned& r0, unsigned& r1, unsigned& r2, unsigned& r3,
                                          const void* p) {
    unsigned addr = (unsigned)__cvta_generic_to_shared(p);
    asm volatile("ldmatrix.sync.aligned.m8n8.x4.trans.shared.b16 {%0,%1,%2,%3}, [%4];"
        : "=r"(r0), "=r"(r1), "=r"(r2), "=r"(r3) : "r"(addr));
}
__device__ __forceinline__ void mma16816(float d[4], const unsigned a[4], const unsigned b[2]) {
    asm volatile("mma.sync.aligned.m16n8k16.row.col.f32.f16.f16.f32 "
        "{%0,%1,%2,%3}, {%4,%5,%6,%7}, {%8,%9}, {%0,%1,%2,%3};"
        : "+f"(d[0]), "+f"(d[1]), "+f"(d[2]), "+f"(d[3])
        : "r"(a[0]), "r"(a[1]), "r"(a[2]), "r"(a[3]), "r"(b[0]), "r"(b[1]));
}

// ---------------- gemm_qk: q = Wqk (32xC) * X; writes fp16 hi/lo + transposed --
__global__ __launch_bounds__(256) void gemm_qk(
    const float* __restrict__ W, const float* __restrict__ X,
    __half* __restrict__ QH, __half* __restrict__ QL,
    __half* __restrict__ QTH, __half* __restrict__ QTL)
{
    __shared__ float Ws[CC][32];
    __shared__ float Xs[64][128];

    const int b  = blockIdx.z;
    const int n0 = blockIdx.x * 128;
    const int tid = threadIdx.x;

    for (int idx = tid; idx < 32 * CC; idx += 256) {
        int o = idx / CC, c = idx % CC;
        Ws[c][o] = W[(size_t)o * CC + c];
    }

    const float* x1 = X + (size_t)b * CC * NN;

    float acc[4][4] = {};
    const int to = tid / 32, tn = tid % 32;

    for (int c0 = 0; c0 < CC; c0 += 64) {
        __syncthreads();
        for (int idx = tid; idx < 64 * 128; idx += 256) {
            int c = idx / 128, n = idx % 128;
            Xs[c][n] = x1[(size_t)(c0 + c) * NN + n0 + n];
        }
        __syncthreads();
#pragma unroll 8
        for (int c = 0; c < 64; c++) {
            float4 w = *(const float4*)&Ws[c0 + c][to * 4];
            float4 x = *(const float4*)&Xs[c][tn * 4];
            fma44(acc, w, x);
        }
    }

    __half h[4][4], l[4][4];
#pragma unroll
    for (int i = 0; i < 4; i++)
#pragma unroll
        for (int j = 0; j < 4; j++) {
            h[i][j] = __float2half_rn(acc[i][j]);
            l[i][j] = __float2half_rn(acc[i][j] - __half2float(h[i][j]));
        }

#pragma unroll
    for (int i = 0; i < 4; i++) {
        int o = to * 4 + i;
        size_t off = ((size_t)b * 32 + o) * NN + n0 + tn * 4;
        __half2 h0 = __halves2half2(h[i][0], h[i][1]);
        __half2 h1 = __halves2half2(h[i][2], h[i][3]);
        uint2 pk; pk.x = *(unsigned*)&h0; pk.y = *(unsigned*)&h1;
        *(uint2*)&QH[off] = pk;
        __half2 l0 = __halves2half2(l[i][0], l[i][1]);
        __half2 l1 = __halves2half2(l[i][2], l[i][3]);
        uint2 pl; pl.x = *(unsigned*)&l0; pl.y = *(unsigned*)&l1;
        *(uint2*)&QL[off] = pl;
    }
#pragma unroll
    for (int j = 0; j < 4; j++) {
        int n = n0 + tn * 4 + j;
        size_t off = ((size_t)b * NN + n) * 32 + to * 4;
        __half2 h0 = __halves2half2(h[0][j], h[1][j]);
        __half2 h1 = __halves2half2(h[2][j], h[3][j]);
        uint2 pk; pk.x = *(unsigned*)&h0; pk.y = *(unsigned*)&h1;
        *(uint2*)&QTH[off] = pk;
        __half2 l0 = __halves2half2(l[0][j], l[1][j]);
        __half2 l1 = __halves2half2(l[2][j], l[3][j]);
        uint2 pl; pl.x = *(unsigned*)&l0; pl.y = *(unsigned*)&l1;
        *(uint2*)&QTL[off] = pl;
    }
}

// ---------------- gemm128: Y[b,o,n] = sum_c W[o,c]*(X1-X2)[b,c,n] + bias ------
__global__ __launch_bounds__(256, 2) void gemm128(
    const float* __restrict__ W, const float* __restrict__ X1,
    const float* __restrict__ X2, const float* __restrict__ bias,
    float* __restrict__ Y, __half* __restrict__ Yh)
{
    __shared__ float  Ws[32][132];
    __shared__ double Xd[32][66];

    const int b  = blockIdx.y;
    const int n0 = blockIdx.x * 128;
    const int tid = threadIdx.x;
    const int tp = tid & 15;
    const int tc = tid >> 4;

    const float* x1 = X1 + (size_t)b * CC * NN;
    const float* x2 = X2 ? X2 + (size_t)b * CC * NN : nullptr;

    ull acc[8][4];
#pragma unroll
    for (int i = 0; i < 8; i++)
#pragma unroll
        for (int j = 0; j < 4; j++) acc[i][j] = 0ull;

    for (int c0 = 0; c0 < CC; c0 += 32) {
        {
            int o = tid & 127, h = tid >> 7;
            const float* wsrc = W + (size_t)o * CC + c0 + h * 16;
            float4 wv[4];
#pragma unroll
            for (int r = 0; r < 4; r++) wv[r] = *(const float4*)&wsrc[r * 4];
#pragma unroll
            for (int r = 0; r < 4; r++) {
                int cbase = h * 16 + r * 4;
                Ws[cbase + 0][o] = wv[r].x;
                Ws[cbase + 1][o] = wv[r].y;
                Ws[cbase + 2][o] = wv[r].z;
                Ws[cbase + 3][o] = wv[r].w;
            }
        }
#pragma unroll
        for (int t = 0; t < 4; t++) {
            int idx = tid + t * 256;
            int c = idx >> 5, q = idx & 31;
            float4 v = *(const float4*)&x1[(size_t)(c0 + c) * NN + n0 + q * 4];
            if (x2) {
                float4 w = *(const float4*)&x2[(size_t)(c0 + c) * NN + n0 + q * 4];
                v.x -= w.x; v.y -= w.y; v.z -= w.z; v.w -= w.w;
            }
            *(double2*)&Xd[c][q * 2] = *(const double2*)&v;
        }
        __syncthreads();
#pragma unroll
        for (int k = 0; k < 32; k++)
            microstep_8x8(acc, &Ws[k][0], &Xd[k][0], tc, tp);
        __syncthreads();
    }

#pragma unroll
    for (int i = 0; i < 8; i++) {
        int o = tc * 8 + i;
        float bi = bias ? bias[o] : 0.f;
#pragma unroll
        for (int j = 0; j < 4; j++) {
            float2 r = unpack2(acc[i][j]);
            r.x += bi; r.y += bi;
            size_t off = ((size_t)b * CC + o) * NN + n0 + 2 * (tp + 16 * j);
            if (Yh) {
                *(__half2*)&Yh[off] = __floats2half2_rn(r.x, r.y);
            } else {
                *(float2*)&Y[off] = r;
            }
        }
    }
}

// ---------------- fused energy + tile softmax ----------------------------------
// tile 64n x 128m. Computes E (hi/lo HMMA), masks, tile row-max, u=exp(v-max),
// writes u fp16 (coalesced via smem staging), emits per-(n,tile) max & sum.
__global__ __launch_bounds__(256, 2) void energy_softmax(
    const __half* __restrict__ QH, const __half* __restrict__ QL,
    const __half* __restrict__ QTH, const __half* __restrict__ QTL,
    const int* __restrict__ mask, __half* __restrict__ U)
{
    __shared__ __half Ah[64][40];
    __shared__ __half Al[64][40];
    __shared__ __half Bh[32][136];
    __shared__ __half Bl[32][136];
    __shared__ __half Us[64][136];
    __shared__ float  redu[64][4];
    __shared__ float  rowmax_s[64];
    __shared__ int    cms[128];
    __shared__ int    rms[64];

    const int b  = blockIdx.z;
    const int n0 = blockIdx.y * 64;
    const int m0 = blockIdx.x * 128;
    const int mt = blockIdx.x;
    const int tid = threadIdx.x;
    const int wid = tid >> 5, lane = tid & 31;
    const int wn = wid & 1, wm = wid >> 1;

    {
        int r = tid >> 2, s = tid & 3;
        size_t off = ((size_t)b * NN + n0 + r) * 32 + s * 8;
        *(uint4*)&Ah[r][s * 8] = *(const uint4*)&QTH[off];
        *(uint4*)&Al[r][s * 8] = *(const uint4*)&QTL[off];
    }
#pragma unroll
    for (int u = 0; u < 2; u++) {
        int idx = tid + u * 256;
        int r = idx >> 4, s = idx & 15;
        size_t off = ((size_t)b * 32 + r) * NN + m0 + s * 8;
        *(uint4*)&Bh[r][s * 8] = *(const uint4*)&QH[off];
        *(uint4*)&Bl[r][s * 8] = *(const uint4*)&QL[off];
    }
    if (tid < 128) cms[tid] = mask[(size_t)b * NN + m0 + tid];
    if (tid < 64)  rms[tid] = mask[(size_t)b * NN + n0 + tid];
    __syncthreads();

    float acc[2][4][4];
#pragma unroll
    for (int i = 0; i < 2; i++)
#pragma unroll
        for (int j = 0; j < 4; j++)
#pragma unroll
            for (int k = 0; k < 4; k++) acc[i][j][k] = 0.f;

    const int lrow = (lane & 7) + ((lane >> 3) & 1) * 8;
    const int lsel = lane >> 4;
    const int g = lane >> 3;
    const int r0l = lane >> 2, c0l = (lane & 3) * 2;

#pragma unroll
    for (int kk = 0; kk < 2; kk++) {
        unsigned ah[2][4], al[2][4];
#pragma unroll
        for (int ci = 0; ci < 2; ci++) {
            ldsm_x4(ah[ci][0], ah[ci][1], ah[ci][2], ah[ci][3],
                    &Ah[wn * 32 + ci * 16 + lrow][kk * 16 + lsel * 8]);
            ldsm_x4(al[ci][0], al[ci][1], al[ci][2], al[ci][3],
                    &Al[wn * 32 + ci * 16 + lrow][kk * 16 + lsel * 8]);
        }
        unsigned bh[4][2], bl[4][2];
#pragma unroll
        for (int h = 0; h < 2; h++) {
            unsigned t0, t1, t2, t3;
            ldsm_x4_t(t0, t1, t2, t3,
                      &Bh[kk * 16 + (g & 1) * 8 + (lane & 7)][wm * 32 + h * 16 + (g >> 1) * 8]);
            bh[h * 2 + 0][0] = t0; bh[h * 2 + 0][1] = t1;
            bh[h * 2 + 1][0] = t2; bh[h * 2 + 1][1] = t3;
            ldsm_x4_t(t0, t1, t2, t3,
                      &Bl[kk * 16 + (g & 1) * 8 + (lane & 7)][wm * 32 + h * 16 + (g >> 1) * 8]);
            bl[h * 2 + 0][0] = t0; bl[h * 2 + 0][1] = t1;
            bl[h * 2 + 1][0] = t2; bl[h * 2 + 1][1] = t3;
        }
#pragma unroll
        for (int ci = 0; ci < 2; ci++)
#pragma unroll
            for (int nf = 0; nf < 4; nf++) {
                mma16816(acc[ci][nf], ah[ci], bh[nf]);
                mma16816(acc[ci][nf], ah[ci], bl[nf]);
                mma16816(acc[ci][nf], al[ci], bh[nf]);
            }
    }

    // mask + tile row-max
    float vmax[2][2];
    vmax[0][0] = NEGV; vmax[0][1] = NEGV; vmax[1][0] = NEGV; vmax[1][1] = NEGV;
#pragma unroll
    for (int ci = 0; ci < 2; ci++)
#pragma unroll
        for (int nf = 0; nf < 4; nf++) {
            int mm = wm * 32 + nf * 8 + c0l;
            int cm0 = cms[mm], cm1 = cms[mm + 1];
#pragma unroll
            for (int h = 0; h < 2; h++) {
                int rm = rms[wn * 32 + ci * 16 + h * 8 + r0l];
                float v0 = (rm && cm0) ? acc[ci][nf][h * 2 + 0] : NEGV;
                float v1 = (rm && cm1) ? acc[ci][nf][h * 2 + 1] : NEGV;
                acc[ci][nf][h * 2 + 0] = v0;
                acc[ci][nf][h * 2 + 1] = v1;
                vmax[ci][h] = fmaxf(vmax[ci][h], fmaxf(v0, v1));
            }
        }
#pragma unroll
    for (int ci = 0; ci < 2; ci++)
#pragma unroll
        for (int h = 0; h < 2; h++) {
            float v = vmax[ci][h];
            v = fmaxf(v, __shfl_xor_sync(0xffffffffu, v, 1));
            v = fmaxf(v, __shfl_xor_sync(0xffffffffu, v, 2));
            vmax[ci][h] = v;
        }
    if ((lane & 3) == 0) {
#pragma unroll
        for (int ci = 0; ci < 2; ci++)
#pragma unroll
            for (int h = 0; h < 2; h++)
                redu[wn * 32 + ci * 16 + h * 8 + r0l][wm] = vmax[ci][h];
    }
    __syncthreads();
    if (tid < 64) {
        float v = fmaxf(fmaxf(redu[tid][0], redu[tid][1]),
                        fmaxf(redu[tid][2], redu[tid][3]));
        rowmax_s[tid] = v;
        g_tmax[((size_t)mt * BB + b) * NN + n0 + tid] = v;
    }
    __syncthreads();

    // exp + stage u to smem + tile row-sum
    float mx_[2][2];
#pragma unroll
    for (int ci = 0; ci < 2; ci++)
#pragma unroll
        for (int h = 0; h < 2; h++)
            mx_[ci][h] = rowmax_s[wn * 32 + ci * 16 + h * 8 + r0l];

    float rsum[2][2] = {{0.f, 0.f}, {0.f, 0.f}};
#pragma unroll
    for (int ci = 0; ci < 2; ci++)
#pragma unroll
        for (int nf = 0; nf < 4; nf++) {
            int mm = wm * 32 + nf * 8 + c0l;
#pragma unroll
            for (int h = 0; h < 2; h++) {
                float u0 = __expf(acc[ci][nf][h * 2 + 0] - mx_[ci][h]);
                float u1 = __expf(acc[ci][nf][h * 2 + 1] - mx_[ci][h]);
                int row = wn * 32 + ci * 16 + h * 8 + r0l;
                *(__half2*)&Us[row][mm] = __floats2half2_rn(u0, u1);
                rsum[ci][h] += u0 + u1;
            }
        }
#pragma unroll
    for (int ci = 0; ci < 2; ci++)
#pragma unroll
        for (int h = 0; h < 2; h++) {
            float v = rsum[ci][h];
            v += __shfl_xor_sync(0xffffffffu, v, 1);
            v += __shfl_xor_sync(0xffffffffu, v, 2);
            rsum[ci][h] = v;
        }
    if ((lane & 3) == 0) {
#pragma unroll
        for (int ci = 0; ci < 2; ci++)
#pragma unroll
            for (int h = 0; h < 2; h++)
                redu[wn * 32 + ci * 16 + h * 8 + r0l][wm] = rsum[ci][h];
    }
    __syncthreads();
    if (tid < 64) {
        float s = (redu[tid][0] + redu[tid][1]) + (redu[tid][2] + redu[tid][3]);
        g_tsum[((size_t)mt * BB + b) * NN + n0 + tid] = s;
    }
    // coalesced U flush
#pragma unroll
    for (int u = 0; u < 4; u++) {
        int idx = tid + u * 256;
        int r = idx >> 4, s = idx & 15;
        *(uint4*)&U[((size_t)b * NN + n0 + r) * NN + m0 + s * 8] = *(uint4*)&Us[r][s * 8];
    }
}

// ---------------- rowscale: f[t][n] = exp(tmax-t - m_row)/rowsum ----------------
__global__ __launch_bounds__(256) void rowscale_kernel()
{
    const int b = blockIdx.y;
    const int n = blockIdx.x * 256 + threadIdx.x;
    float mx[32];
    float m_row;
#pragma unroll
    for (int t = 0; t < 32; t++) {
        mx[t] = g_tmax[((size_t)t * BB + b) * NN + n];
        m_row = (t == 0) ? mx[0] : fmaxf(m_row, mx[t]);
    }
    float s = 0.f;
    float ex[32];
#pragma unroll
    for (int t = 0; t < 32; t++) {
        ex[t] = __expf(mx[t] - m_row);
        s += ex[t] * g_tsum[((size_t)t * BB + b) * NN + n];
    }
    float inv = 1.f / s;
#pragma unroll
    for (int t = 0; t < 32; t++)
        g_rowscale[((size_t)t * BB + b) * NN + n] = ex[t] * inv;
}

// ---------------- attn apply via HMMA, f-scaled, in-CTA colsum/colinv ----------
// 256 threads = 8 warps (4c x 2m), block tile 128c x 64m, full k sweep.
__global__ __launch_bounds__(256, 2) void apply_hmma(
    const __half* __restrict__ XVH, const __half* __restrict__ U,
    float* __restrict__ XR)
{
    __shared__ __half XVs[128][72];
    __shared__ __half As[64][72];
    __shared__ float  cs_s[32][68];
    __shared__ float  cinv_s[64];

    const int b  = blockIdx.y;
    const int m0 = blockIdx.x * 64;
    const int t  = blockIdx.x >> 1;           // energy m-tile (128-wide)
    const int tid = threadIdx.x;
    const int wid = tid >> 5, lane = tid & 31;
    const int wc = wid & 3, wm = wid >> 2;

    const __half* xv = XVH + (size_t)b * CC * NN;
    const __half* at = U + (size_t)b * NN * NN;
    const float* fscale = g_rowscale + ((size_t)t * BB + b) * NN;

    float acc[2][4][4];
#pragma unroll
    for (int i = 0; i < 2; i++)
#pragma unroll
        for (int j = 0; j < 4; j++)
#pragma unroll
            for (int k = 0; k < 4; k++) acc[i][j][k] = 0.f;

    float2 cs2[4];
#pragma unroll
    for (int j = 0; j < 4; j++) cs2[j] = make_float2(0.f, 0.f);

    const int lrow = (lane & 7) + ((lane >> 3) & 1) * 8;
    const int lsel = lane >> 4;
    const int g = lane >> 3;

    for (int k0 = 0; k0 < NN; k0 += 64) {
#pragma unroll
        for (int u = 0; u < 4; u++) {
            int idx = tid + u * 256;
            int r = idx >> 3, s = idx & 7;
            *(uint4*)&XVs[r][s * 8] = *(const uint4*)&xv[(size_t)r * NN + k0 + s * 8];
        }
#pragma unroll
        for (int u = 0; u < 2; u++) {
            int idx = tid + u * 256;
            int r = idx >> 3, s = idx & 7;
            uint4 raw = *(const uint4*)&at[(size_t)(k0 + r) * NN + m0 + s * 8];
            float fr = fscale[k0 + r];
            const __half2* hp = (const __half2*)&raw;
            __half2 outh[4];
#pragma unroll
            for (int j = 0; j < 4; j++) {
                float2 v = __half22float2(hp[j]);
                v.x *= fr; v.y *= fr;
                cs2[j].x += v.x; cs2[j].y += v.y;
                outh[j] = __floats2half2_rn(v.x, v.y);
            }
            *(uint4*)&As[r][s * 8] = *(const uint4*)&outh[0];
        }
        __syncthreads();

#pragma unroll
        for (int kk = 0; kk < 4; kk++) {
            unsigned a[2][4];
#pragma unroll
            for (int ci = 0; ci < 2; ci++)
                ldsm_x4(a[ci][0], a[ci][1], a[ci][2], a[ci][3],
                        &XVs[wc * 32 + ci * 16 + lrow][kk * 16 + lsel * 8]);
            unsigned bf[4][2];
#pragma unroll
            for (int h = 0; h < 2; h++) {
                unsigned t0, t1, t2, t3;
                ldsm_x4_t(t0, t1, t2, t3,
                          &As[kk * 16 + (g & 1) * 8 + (lane & 7)][wm * 32 + h * 16 + (g >> 1) * 8]);
                bf[h * 2 + 0][0] = t0; bf[h * 2 + 0][1] = t1;
                bf[h * 2 + 1][0] = t2; bf[h * 2 + 1][1] = t3;
            }
#pragma unroll
            for (int ci = 0; ci < 2; ci++)
#pragma unroll
                for (int nf = 0; nf < 4; nf++)
                    mma16816(acc[ci][nf], a[ci], bf[nf]);
        }
        __syncthreads();
    }

    // in-CTA column sums -> colinv (note: both u-iterations share column set s*8..)
    {
        int gg = tid >> 3, s = tid & 7;
#pragma unroll
        for (int j = 0; j < 4; j++) {
            cs_s[gg][s * 8 + 2 * j]     = cs2[j].x;
            cs_s[gg][s * 8 + 2 * j + 1] = cs2[j].y;
        }
    }
    __syncthreads();
    if (tid < 64) {
        float tot = 0.f;
#pragma unroll
        for (int gg = 0; gg < 32; gg++) tot += cs_s[gg][tid];
        cinv_s[tid] = 1.f / (1e-9f + tot);
    }
    __syncthreads();

    const int r0l = lane >> 2, c0l = (lane & 3) * 2;
#pragma unroll
    for (int ci = 0; ci < 2; ci++) {
#pragma unroll
        for (int nf = 0; nf < 4; nf++) {
            int c = wc * 32 + ci * 16 + r0l;
            int mm = wm * 32 + nf * 8 + c0l;
            float2 cv = *(const float2*)&cinv_s[mm];
            float2 lo = make_float2(acc[ci][nf][0] * cv.x, acc[ci][nf][1] * cv.y);
            *(float2*)&XR[((size_t)b * CC + c) * NN + m0 + mm] = lo;
            float2 hi = make_float2(acc[ci][nf][2] * cv.x, acc[ci][nf][3] * cv.y);
            *(float2*)&XR[((size_t)b * CC + c + 8) * NN + m0 + mm] = hi;
        }
    }
}

// ---------------- BN stats: 8-way partials + finalize ---------------------------
__global__ __launch_bounds__(256) void bn_part_kernel(const float* __restrict__ Y)
{
    const int c = blockIdx.x;
    const int s = blockIdx.y;
    const int b = s >> 1;
    const int n0 = (s & 1) * 2048;
    const float* p = Y + ((size_t)b * CC + c) * NN + n0;
    const int tid = threadIdx.x;
    float sum = 0.f, sq = 0.f;
#pragma unroll
    for (int i = 0; i < 8; i++) {
        float v = p[tid + i * 256];
        sum += v; sq += v * v;
    }
    sum = warp_red_sum(sum); sq = warp_red_sum(sq);
    __shared__ float r1[8], r2[8];
    if ((tid & 31) == 0) { r1[tid >> 5] = sum; r2[tid >> 5] = sq; }
    __syncthreads();
    if (tid == 0) {
        float ts = 0.f, t2 = 0.f;
#pragma unroll
        for (int i = 0; i < 8; i++) { ts += r1[i]; t2 += r2[i]; }
        g_bnp1[s][c] = ts;
        g_bnp2[s][c] = t2;
    }
}

__global__ void bn_finalize_kernel(const float* __restrict__ gam, const float* __restrict__ bet)
{
    const int c = threadIdx.x;
    float ts = 0.f, t2 = 0.f;
#pragma unroll
    for (int s = 0; s < 8; s++) { ts += g_bnp1[s][c]; t2 += g_bnp2[s][c]; }
    const float invN = 1.f / (float)(BB * NN);
    float mean = ts * invN;
    float var  = t2 * invN - mean * mean;
    float sc = gam[c] * rsqrtf(var + 1e-5f);
    g_scale[c] = sc;
    g_shift[c] = bet[c] - mean * sc;
}

// ---------------- BN apply (+relu) [+residual into h and output slab] -----------
__global__ __launch_bounds__(256) void bn_apply_kernel(
    const float* __restrict__ Y, float* __restrict__ H,
    float* __restrict__ OUT, int layer)
{
    size_t f = ((size_t)blockIdx.x * 256 + threadIdx.x) * 4;
    int n = (int)(f % NN);
    int c = (int)((f / NN) % CC);
    int b = (int)(f / ((size_t)NN * CC));
    float sc = g_scale[c], sh = g_shift[c];
    float4 y = *(const float4*)&Y[f];
    float4 r;
    r.x = fmaxf(fmaf(y.x, sc, sh), 0.f);
    r.y = fmaxf(fmaf(y.y, sc, sh), 0.f);
    r.z = fmaxf(fmaf(y.z, sc, sh), 0.f);
    r.w = fmaxf(fmaf(y.w, sc, sh), 0.f);
    if (OUT) {
        float4 h = *(const float4*)&H[f];
        r.x += h.x; r.y += h.y; r.z += h.z; r.w += h.w;
        *(float4*)&H[f] = r;
        *(float4*)&OUT[(((size_t)b * 4 * CC) + (size_t)layer * CC + c) * NN + n] = r;
    } else {
        *(float4*)&H[f] = r;
    }
}

// ---------------- launch ---------------------------------------------------------
extern "C" void kernel_launch(void* const* d_in, const int* in_sizes, int n_in,
                              void* d_out, int out_size)
{
    const float* x    = (const float*)d_in[0];
    const int*   mask = (const int*)  d_in[1];
    const float* w1   = (const float*)d_in[2];
    const float* g1   = (const float*)d_in[3];
    const float* b1   = (const float*)d_in[4];
    const float* w2   = (const float*)d_in[5];
    const float* g2   = (const float*)d_in[6];
    const float* b2   = (const float*)d_in[7];
    const float* wqk  = (const float*)d_in[8];
    const float* wv   = (const float*)d_in[9];
    const float* bv   = (const float*)d_in[10];
    const float* wt   = (const float*)d_in[11];
    const float* bt   = (const float*)d_in[12];
    const float* sg   = (const float*)d_in[13];
    const float* sb   = (const float*)d_in[14];
    float* out = (float*)d_out;

    float *p_h, *p_y, *p_xr;
    __half *p_xvh, *p_u, *p_qh, *p_ql, *p_qth, *p_qtl;
    cudaGetSymbolAddress((void**)&p_h,   g_h);
    cudaGetSymbolAddress((void**)&p_y,   g_y);
    cudaGetSymbolAddress((void**)&p_xvh, g_xvh);
    cudaGetSymbolAddress((void**)&p_xr,  g_xr);
    cudaGetSymbolAddress((void**)&p_u,   g_u);
    cudaGetSymbolAddress((void**)&p_qh,  g_qh);
    cudaGetSymbolAddress((void**)&p_ql,  g_ql);
    cudaGetSymbolAddress((void**)&p_qth, g_qth);
    cudaGetSymbolAddress((void**)&p_qtl, g_qtl);

    const dim3 blk256(256);
    const dim3 grid_g128(NN / 128, BB);
    const dim3 grid_qk(NN / 128, 1, BB);
    const dim3 grid_es(NN / 128, NN / 64, BB);
    const dim3 grid_rs(NN / 256, BB);
    const dim3 grid_ap(NN / 64, BB);
    const dim3 grid_bp(CC, 8);
    const dim3 grid_ba((unsigned)(((size_t)BB * CC * NN / 4) / 256));

    // head: two conv+BN+relu
    gemm128<<<grid_g128, blk256>>>(w1, x, nullptr, nullptr, p_y, nullptr);
    bn_part_kernel<<<grid_bp, blk256>>>(p_y);
    bn_finalize_kernel<<<1, CC>>>(g1, b1);
    bn_apply_kernel<<<grid_ba, blk256>>>(p_y, p_h, nullptr, 0);

    gemm128<<<grid_g128, blk256>>>(w2, p_h, nullptr, nullptr, p_y, nullptr);
    bn_part_kernel<<<grid_bp, blk256>>>(p_y);
    bn_finalize_kernel<<<1, CC>>>(g2, b2);
    bn_apply_kernel<<<grid_ba, blk256>>>(p_y, p_h, nullptr, 0);

    // 4 offset-attention layers
    for (int i = 0; i < 4; i++) {
        gemm_qk<<<grid_qk, blk256>>>(wqk + (size_t)i * 32 * CC, p_h, p_qh, p_ql, p_qth, p_qtl);
        energy_softmax<<<grid_es, blk256>>>(p_qh, p_ql, p_qth, p_qtl, mask, p_u);
        rowscale_kernel<<<grid_rs, blk256>>>();
        gemm128<<<grid_g128, blk256>>>(wv + (size_t)i * CC * CC, p_h, nullptr, bv + (size_t)i * CC,
                                       nullptr, p_xvh);
        apply_hmma<<<grid_ap, blk256>>>(p_xvh, p_u, p_xr);
        gemm128<<<grid_g128, blk256>>>(wt + (size_t)i * CC * CC, p_h, p_xr, bt + (size_t)i * CC,
                                       p_y, nullptr);
        bn_part_kernel<<<grid_bp, blk256>>>(p_y);
        bn_finalize_kernel<<<1, CC>>>(sg + (size_t)i * CC, sb + (size_t)i * CC);
        bn_apply_kernel<<<grid_ba, blk256>>>(p_y, p_h, out, i);
    }
}

// round 8
// speedup vs baseline: 1.3882x; 1.0018x over previous
#include <cuda_runtime.h>
#include <cuda_fp16.h>
#include <cstdint>
#include <cstddef>

#define NN 4096
#define CC 128
#define BB 4
#define NEGV (-9e15f)
#define LOG2E 1.4426950408889634f
#define FSCALE 256.0f

typedef unsigned long long ull;

// ---------------- scratch (device globals: no allocation allowed) -----------
__device__ float  g_h[(size_t)BB * CC * NN];                 // 8 MB
__device__ float  g_y[(size_t)BB * CC * NN];                 // 8 MB
__device__ __half g_qh[(size_t)BB * 32 * NN];                // 1 MB q hi [b][o][n]
__device__ __half g_ql[(size_t)BB * 32 * NN];                // 1 MB q lo
__device__ __half g_qth[(size_t)BB * NN * 32];               // 1 MB q hi transposed
__device__ __half g_qtl[(size_t)BB * NN * 32];               // 1 MB q lo transposed
__device__ __half g_xvh[(size_t)BB * CC * NN];               // 4 MB value proj fp16
__device__ float  g_xr[(size_t)BB * CC * NN];                // 8 MB
__device__ __half g_u[(size_t)BB * NN * NN];                 // 128 MB tile-softmaxed exp fp16
__device__ float  g_tmax[(size_t)32 * BB * NN];              // per-(m-tile) row max
__device__ float  g_tsum[(size_t)32 * BB * NN];              // per-(m-tile) row expsum
__device__ __half g_rowscale[(size_t)32 * BB * NN];          // f[t][b][n] fp16, x256
__device__ float  g_scale[CC];
__device__ float  g_shift[CC];
__device__ float  g_bnpS[32][BB][CC];                        // per-(nblk,b) channel sums
__device__ float  g_bnpQ[32][BB][CC];                        // per-(nblk,b) channel sumsq

// ---------------- helpers ----------------------------------------------------
__device__ __forceinline__ void fma2(ull& acc, ull a, ull b) {
    asm("fma.rn.f32x2 %0, %1, %2, %0;" : "+l"(acc) : "l"(a), "l"(b));
}
__device__ __forceinline__ ull pack2(float v) {
    ull r;
    unsigned u = __float_as_uint(v);
    asm("mov.b64 %0, {%1, %1};" : "=l"(r) : "r"(u));
    return r;
}
__device__ __forceinline__ float2 unpack2(ull v) {
    unsigned lo, hi;
    asm("mov.b64 {%0, %1}, %2;" : "=r"(lo), "=r"(hi) : "l"(v));
    return make_float2(__uint_as_float(lo), __uint_as_float(hi));
}
__device__ __forceinline__ __half2 h2_ex2(__half2 x) {
    unsigned xi = *(unsigned*)&x;
    unsigned ri;
    asm("ex2.approx.f16x2 %0, %1;" : "=r"(ri) : "r"(xi));
    return *(__half2*)&ri;
}

__device__ __forceinline__ void fma44(float acc[4][4], float4 w, float4 x) {
    acc[0][0] += w.x * x.x; acc[0][1] += w.x * x.y; acc[0][2] += w.x * x.z; acc[0][3] += w.x * x.w;
    acc[1][0] += w.y * x.x; acc[1][1] += w.y * x.y; acc[1][2] += w.y * x.z; acc[1][3] += w.y * x.w;
    acc[2][0] += w.z * x.x; acc[2][1] += w.z * x.y; acc[2][2] += w.z * x.z; acc[2][3] += w.z * x.w;
    acc[3][0] += w.w * x.x; acc[3][1] += w.w * x.y; acc[3][2] += w.w * x.z; acc[3][3] += w.w * x.w;
}

__device__ __forceinline__ void microstep_8x8(
    ull acc[8][4], const float* __restrict__ rowS, const double* __restrict__ pairS,
    int tc, int tp)
{
    float4 xa = *(const float4*)&rowS[tc * 8];
    float4 xb = *(const float4*)&rowS[tc * 8 + 4];
    ull xc[8];
    xc[0] = pack2(xa.x); xc[1] = pack2(xa.y); xc[2] = pack2(xa.z); xc[3] = pack2(xa.w);
    xc[4] = pack2(xb.x); xc[5] = pack2(xb.y); xc[6] = pack2(xb.z); xc[7] = pack2(xb.w);
    ull af[4];
#pragma unroll
    for (int j = 0; j < 4; j++) af[j] = *(const ull*)&pairS[tp + 16 * j];
#pragma unroll
    for (int i = 0; i < 8; i++)
#pragma unroll
        for (int j = 0; j < 4; j++) fma2(acc[i][j], xc[i], af[j]);
}

// ---------------- HMMA helpers -------------------------------------------------
__device__ __forceinline__ void ldsm_x4(unsigned& r0, unsigned& r1, unsigned& r2, unsigned& r3,
                                        const void* p) {
    unsigned addr = (unsigned)__cvta_generic_to_shared(p);
    asm volatile("ldmatrix.sync.aligned.m8n8.x4.shared.b16 {%0,%1,%2,%3}, [%4];"
        : "=r"(r0), "=r"(r1), "=r"(r2), "=r"(r3) : "r"(addr));
}
__device__ __forceinline__ void ldsm_x4_t(unsigned& r0, unsigned& r1, unsigned& r2, unsigned& r3,
                                          const void* p) {
    unsigned addr = (unsigned)__cvta_generic_to_shared(p);
    asm volatile("ldmatrix.sync.aligned.m8n8.x4.trans.shared.b16 {%0,%1,%2,%3}, [%4];"
        : "=r"(r0), "=r"(r1), "=r"(r2), "=r"(r3) : "r"(addr));
}
__device__ __forceinline__ void mma16816(float d[4], const unsigned a[4], const unsigned b[2]) {
    asm volatile("mma.sync.aligned.m16n8k16.row.col.f32.f16.f16.f32 "
        "{%0,%1,%2,%3}, {%4,%5,%6,%7}, {%8,%9}, {%0,%1,%2,%3};"
        : "+f"(d[0]), "+f"(d[1]), "+f"(d[2]), "+f"(d[3])
        : "r"(a[0]), "r"(a[1]), "r"(a[2]), "r"(a[3]), "r"(b[0]), "r"(b[1]));
}

// ---------------- gemm_qk: q = Wqk (32xC) * X; writes fp16 hi/lo + transposed --
__global__ __launch_bounds__(256) void gemm_qk(
    const float* __restrict__ W, const float* __restrict__ X,
    __half* __restrict__ QH, __half* __restrict__ QL,
    __half* __restrict__ QTH, __half* __restrict__ QTL)
{
    __shared__ float Ws[CC][32];
    __shared__ float Xs[64][128];

    const int b  = blockIdx.z;
    const int n0 = blockIdx.x * 128;
    const int tid = threadIdx.x;

    for (int idx = tid; idx < 32 * CC; idx += 256) {
        int o = idx / CC, c = idx % CC;
        Ws[c][o] = W[(size_t)o * CC + c];
    }

    const float* x1 = X + (size_t)b * CC * NN;

    float acc[4][4] = {};
    const int to = tid / 32, tn = tid % 32;

    for (int c0 = 0; c0 < CC; c0 += 64) {
        __syncthreads();
        for (int idx = tid; idx < 64 * 128; idx += 256) {
            int c = idx / 128, n = idx % 128;
            Xs[c][n] = x1[(size_t)(c0 + c) * NN + n0 + n];
        }
        __syncthreads();
#pragma unroll 8
        for (int c = 0; c < 64; c++) {
            float4 w = *(const float4*)&Ws[c0 + c][to * 4];
            float4 x = *(const float4*)&Xs[c][tn * 4];
            fma44(acc, w, x);
        }
    }

    __half h[4][4], l[4][4];
#pragma unroll
    for (int i = 0; i < 4; i++)
#pragma unroll
        for (int j = 0; j < 4; j++) {
            h[i][j] = __float2half_rn(acc[i][j]);
            l[i][j] = __float2half_rn(acc[i][j] - __half2float(h[i][j]));
        }

#pragma unroll
    for (int i = 0; i < 4; i++) {
        int o = to * 4 + i;
        size_t off = ((size_t)b * 32 + o) * NN + n0 + tn * 4;
        __half2 h0 = __halves2half2(h[i][0], h[i][1]);
        __half2 h1 = __halves2half2(h[i][2], h[i][3]);
        uint2 pk; pk.x = *(unsigned*)&h0; pk.y = *(unsigned*)&h1;
        *(uint2*)&QH[off] = pk;
        __half2 l0 = __halves2half2(l[i][0], l[i][1]);
        __half2 l1 = __halves2half2(l[i][2], l[i][3]);
        uint2 pl; pl.x = *(unsigned*)&l0; pl.y = *(unsigned*)&l1;
        *(uint2*)&QL[off] = pl;
    }
#pragma unroll
    for (int j = 0; j < 4; j++) {
        int n = n0 + tn * 4 + j;
        size_t off = ((size_t)b * NN + n) * 32 + to * 4;
        __half2 h0 = __halves2half2(h[0][j], h[1][j]);
        __half2 h1 = __halves2half2(h[2][j], h[3][j]);
        uint2 pk; pk.x = *(unsigned*)&h0; pk.y = *(unsigned*)&h1;
        *(uint2*)&QTH[off] = pk;
        __half2 l0 = __halves2half2(l[0][j], l[1][j]);
        __half2 l1 = __halves2half2(l[2][j], l[3][j]);
        uint2 pl; pl.x = *(unsigned*)&l0; pl.y = *(unsigned*)&l1;
        *(uint2*)&QTL[off] = pl;
    }
}

// ---------------- gemm128 with fused BN partial stats --------------------------
// Y[b,o,n] = sum_c W[o,c]*(X1-X2)[b,c,n] + bias. fp32 path emits channel partials.
__global__ __launch_bounds__(256, 2) void gemm128(
    const float* __restrict__ W, const float* __restrict__ X1,
    const float* __restrict__ X2, const float* __restrict__ bias,
    float* __restrict__ Y, __half* __restrict__ Yh)
{
    __shared__ float  Ws[32][132];
    __shared__ double Xd[32][66];

    const int b  = blockIdx.y;
    const int nb = blockIdx.x;
    const int n0 = nb * 128;
    const int tid = threadIdx.x;
    const int tp = tid & 15;
    const int tc = tid >> 4;

    const float* x1 = X1 + (size_t)b * CC * NN;
    const float* x2 = X2 ? X2 + (size_t)b * CC * NN : nullptr;

    ull acc[8][4];
#pragma unroll
    for (int i = 0; i < 8; i++)
#pragma unroll
        for (int j = 0; j < 4; j++) acc[i][j] = 0ull;

    for (int c0 = 0; c0 < CC; c0 += 32) {
        {
            int o = tid & 127, h = tid >> 7;
            const float* wsrc = W + (size_t)o * CC + c0 + h * 16;
            float4 wv[4];
#pragma unroll
            for (int r = 0; r < 4; r++) wv[r] = *(const float4*)&wsrc[r * 4];
#pragma unroll
            for (int r = 0; r < 4; r++) {
                int cbase = h * 16 + r * 4;
                Ws[cbase + 0][o] = wv[r].x;
                Ws[cbase + 1][o] = wv[r].y;
                Ws[cbase + 2][o] = wv[r].z;
                Ws[cbase + 3][o] = wv[r].w;
            }
        }
#pragma unroll
        for (int t = 0; t < 4; t++) {
            int idx = tid + t * 256;
            int c = idx >> 5, q = idx & 31;
            float4 v = *(const float4*)&x1[(size_t)(c0 + c) * NN + n0 + q * 4];
            if (x2) {
                float4 w = *(const float4*)&x2[(size_t)(c0 + c) * NN + n0 + q * 4];
                v.x -= w.x; v.y -= w.y; v.z -= w.z; v.w -= w.w;
            }
            *(double2*)&Xd[c][q * 2] = *(const double2*)&v;
        }
        __syncthreads();
#pragma unroll
        for (int k = 0; k < 32; k++)
            microstep_8x8(acc, &Ws[k][0], &Xd[k][0], tc, tp);
        __syncthreads();
    }

    float s_[8], q_[8];
#pragma unroll
    for (int i = 0; i < 8; i++) { s_[i] = 0.f; q_[i] = 0.f; }

#pragma unroll
    for (int i = 0; i < 8; i++) {
        int o = tc * 8 + i;
        float bi = bias ? bias[o] : 0.f;
#pragma unroll
        for (int j = 0; j < 4; j++) {
            float2 r = unpack2(acc[i][j]);
            r.x += bi; r.y += bi;
            size_t off = ((size_t)b * CC + o) * NN + n0 + 2 * (tp + 16 * j);
            if (Yh) {
                *(__half2*)&Yh[off] = __floats2half2_rn(r.x, r.y);
            } else {
                *(float2*)&Y[off] = r;
                s_[i] += r.x + r.y;
                q_[i] += r.x * r.x + r.y * r.y;
            }
        }
    }

    if (!Yh) {
        // reduce across the 16 threads sharing this tc (same warp half)
#pragma unroll
        for (int i = 0; i < 8; i++) {
#pragma unroll
            for (int off = 8; off > 0; off >>= 1) {
                s_[i] += __shfl_xor_sync(0xffffffffu, s_[i], off);
                q_[i] += __shfl_xor_sync(0xffffffffu, q_[i], off);
            }
        }
        if (tp == 0) {
#pragma unroll
            for (int i = 0; i < 8; i++) {
                g_bnpS[nb][b][tc * 8 + i] = s_[i];
                g_bnpQ[nb][b][tc * 8 + i] = q_[i];
            }
        }
    }
}

// ---------------- fused energy + tile softmax (f16x2 ex2) ----------------------
__global__ __launch_bounds__(256, 2) void energy_softmax(
    const __half* __restrict__ QH, const __half* __restrict__ QL,
    const __half* __restrict__ QTH, const __half* __restrict__ QTL,
    const int* __restrict__ mask, __half* __restrict__ U)
{
    __shared__ __half Ah[64][40];
    __shared__ __half Al[64][40];
    __shared__ __half Bh[32][136];
    __shared__ __half Bl[32][136];
    __shared__ __half Us[64][136];
    __shared__ float  redu[64][4];
    __shared__ float  rowmax_s[64];
    __shared__ int    cms[128];
    __shared__ int    rms[64];

    const int b  = blockIdx.z;
    const int n0 = blockIdx.y * 64;
    const int m0 = blockIdx.x * 128;
    const int mt = blockIdx.x;
    const int tid = threadIdx.x;
    const int wid = tid >> 5, lane = tid & 31;
    const int wn = wid & 1, wm = wid >> 1;

    {
        int r = tid >> 2, s = tid & 3;
        size_t off = ((size_t)b * NN + n0 + r) * 32 + s * 8;
        *(uint4*)&Ah[r][s * 8] = *(const uint4*)&QTH[off];
        *(uint4*)&Al[r][s * 8] = *(const uint4*)&QTL[off];
    }
#pragma unroll
    for (int u = 0; u < 2; u++) {
        int idx = tid + u * 256;
        int r = idx >> 4, s = idx & 15;
        size_t off = ((size_t)b * 32 + r) * NN + m0 + s * 8;
        *(uint4*)&Bh[r][s * 8] = *(const uint4*)&QH[off];
        *(uint4*)&Bl[r][s * 8] = *(const uint4*)&QL[off];
    }
    if (tid < 128) cms[tid] = mask[(size_t)b * NN + m0 + tid];
    if (tid < 64)  rms[tid] = mask[(size_t)b * NN + n0 + tid];
    __syncthreads();

    float acc[2][4][4];
#pragma unroll
    for (int i = 0; i < 2; i++)
#pragma unroll
        for (int j = 0; j < 4; j++)
#pragma unroll
            for (int k = 0; k < 4; k++) acc[i][j][k] = 0.f;

    const int lrow = (lane & 7) + ((lane >> 3) & 1) * 8;
    const int lsel = lane >> 4;
    const int g = lane >> 3;
    const int r0l = lane >> 2, c0l = (lane & 3) * 2;

#pragma unroll
    for (int kk = 0; kk < 2; kk++) {
        unsigned ah[2][4], al[2][4];
#pragma unroll
        for (int ci = 0; ci < 2; ci++) {
            ldsm_x4(ah[ci][0], ah[ci][1], ah[ci][2], ah[ci][3],
                    &Ah[wn * 32 + ci * 16 + lrow][kk * 16 + lsel * 8]);
            ldsm_x4(al[ci][0], al[ci][1], al[ci][2], al[ci][3],
                    &Al[wn * 32 + ci * 16 + lrow][kk * 16 + lsel * 8]);
        }
        unsigned bh[4][2], bl[4][2];
#pragma unroll
        for (int h = 0; h < 2; h++) {
            unsigned t0, t1, t2, t3;
            ldsm_x4_t(t0, t1, t2, t3,
                      &Bh[kk * 16 + (g & 1) * 8 + (lane & 7)][wm * 32 + h * 16 + (g >> 1) * 8]);
            bh[h * 2 + 0][0] = t0; bh[h * 2 + 0][1] = t1;
            bh[h * 2 + 1][0] = t2; bh[h * 2 + 1][1] = t3;
            ldsm_x4_t(t0, t1, t2, t3,
                      &Bl[kk * 16 + (g & 1) * 8 + (lane & 7)][wm * 32 + h * 16 + (g >> 1) * 8]);
            bl[h * 2 + 0][0] = t0; bl[h * 2 + 0][1] = t1;
            bl[h * 2 + 1][0] = t2; bl[h * 2 + 1][1] = t3;
        }
#pragma unroll
        for (int ci = 0; ci < 2; ci++)
#pragma unroll
            for (int nf = 0; nf < 4; nf++) {
                mma16816(acc[ci][nf], ah[ci], bh[nf]);
                mma16816(acc[ci][nf], ah[ci], bl[nf]);
                mma16816(acc[ci][nf], al[ci], bh[nf]);
            }
    }

    // mask + tile row-max
    float vmax[2][2];
    vmax[0][0] = NEGV; vmax[0][1] = NEGV; vmax[1][0] = NEGV; vmax[1][1] = NEGV;
#pragma unroll
    for (int ci = 0; ci < 2; ci++)
#pragma unroll
        for (int nf = 0; nf < 4; nf++) {
            int mm = wm * 32 + nf * 8 + c0l;
            int cm0 = cms[mm], cm1 = cms[mm + 1];
#pragma unroll
            for (int h = 0; h < 2; h++) {
                int rm = rms[wn * 32 + ci * 16 + h * 8 + r0l];
                float v0 = (rm && cm0) ? acc[ci][nf][h * 2 + 0] : NEGV;
                float v1 = (rm && cm1) ? acc[ci][nf][h * 2 + 1] : NEGV;
                acc[ci][nf][h * 2 + 0] = v0;
                acc[ci][nf][h * 2 + 1] = v1;
                vmax[ci][h] = fmaxf(vmax[ci][h], fmaxf(v0, v1));
            }
        }
#pragma unroll
    for (int ci = 0; ci < 2; ci++)
#pragma unroll
        for (int h = 0; h < 2; h++) {
            float v = vmax[ci][h];
            v = fmaxf(v, __shfl_xor_sync(0xffffffffu, v, 1));
            v = fmaxf(v, __shfl_xor_sync(0xffffffffu, v, 2));
            vmax[ci][h] = v;
        }
    if ((lane & 3) == 0) {
#pragma unroll
        for (int ci = 0; ci < 2; ci++)
#pragma unroll
            for (int h = 0; h < 2; h++)
                redu[wn * 32 + ci * 16 + h * 8 + r0l][wm] = vmax[ci][h];
    }
    __syncthreads();
    if (tid < 64) {
        float v = fmaxf(fmaxf(redu[tid][0], redu[tid][1]),
                        fmaxf(redu[tid][2], redu[tid][3]));
        rowmax_s[tid] = v;
        g_tmax[((size_t)mt * BB + b) * NN + n0 + tid] = v;
    }
    __syncthreads();

    // u = 2^((v-max)*log2e) via f16x2 ex2; stage to smem; tile row-sum of stored u
    float mx_[2][2];
#pragma unroll
    for (int ci = 0; ci < 2; ci++)
#pragma unroll
        for (int h = 0; h < 2; h++)
            mx_[ci][h] = rowmax_s[wn * 32 + ci * 16 + h * 8 + r0l];

    float rsum[2][2] = {{0.f, 0.f}, {0.f, 0.f}};
#pragma unroll
    for (int ci = 0; ci < 2; ci++)
#pragma unroll
        for (int nf = 0; nf < 4; nf++) {
            int mm = wm * 32 + nf * 8 + c0l;
#pragma unroll
            for (int h = 0; h < 2; h++) {
                // exact-zero when fully-masked row: (NEGV - NEGV) = 0 -> ex2(0)=1
                float x0 = (acc[ci][nf][h * 2 + 0] - mx_[ci][h]) * LOG2E;
                float x1 = (acc[ci][nf][h * 2 + 1] - mx_[ci][h]) * LOG2E;
                __half2 u2 = h2_ex2(__floats2half2_rn(x0, x1));
                int row = wn * 32 + ci * 16 + h * 8 + r0l;
                *(__half2*)&Us[row][mm] = u2;
                float2 uf = __half22float2(u2);
                rsum[ci][h] += uf.x + uf.y;
            }
        }
#pragma unroll
    for (int ci = 0; ci < 2; ci++)
#pragma unroll
        for (int h = 0; h < 2; h++) {
            float v = rsum[ci][h];
            v += __shfl_xor_sync(0xffffffffu, v, 1);
            v += __shfl_xor_sync(0xffffffffu, v, 2);
            rsum[ci][h] = v;
        }
    if ((lane & 3) == 0) {
#pragma unroll
        for (int ci = 0; ci < 2; ci++)
#pragma unroll
            for (int h = 0; h < 2; h++)
                redu[wn * 32 + ci * 16 + h * 8 + r0l][wm] = rsum[ci][h];
    }
    __syncthreads();
    if (tid < 64) {
        float s = (redu[tid][0] + redu[tid][1]) + (redu[tid][2] + redu[tid][3]);
        g_tsum[((size_t)mt * BB + b) * NN + n0 + tid] = s;
    }
    // coalesced U flush
#pragma unroll
    for (int u = 0; u < 4; u++) {
        int idx = tid + u * 256;
        int r = idx >> 4, s = idx & 15;
        *(uint4*)&U[((size_t)b * NN + n0 + r) * NN + m0 + s * 8] = *(uint4*)&Us[r][s * 8];
    }
}

// ---------------- rowscale: f[t][n] = FSCALE*exp(tmax_t - m_row)/rowsum (fp16) --
__global__ __launch_bounds__(256) void rowscale_kernel()
{
    const int b = blockIdx.y;
    const int n = blockIdx.x * 256 + threadIdx.x;
    float mx[32];
    float m_row;
#pragma unroll
    for (int t = 0; t < 32; t++) {
        mx[t] = g_tmax[((size_t)t * BB + b) * NN + n];
        m_row = (t == 0) ? mx[0] : fmaxf(m_row, mx[t]);
    }
    float s = 0.f;
    float ex[32];
#pragma unroll
    for (int t = 0; t < 32; t++) {
        ex[t] = __expf(mx[t] - m_row);
        s += ex[t] * g_tsum[((size_t)t * BB + b) * NN + n];
    }
    float inv = FSCALE / s;
#pragma unroll
    for (int t = 0; t < 32; t++)
        g_rowscale[((size_t)t * BB + b) * NN + n] = __float2half_rn(ex[t] * inv);
}

// ---------------- attn apply via HMMA, hmul2 f-scaled, in-CTA colsum/colinv ----
__global__ __launch_bounds__(256, 2) void apply_hmma(
    const __half* __restrict__ XVH, const __half* __restrict__ U,
    float* __restrict__ XR)
{
    __shared__ __half XVs[128][72];
    __shared__ __half As[64][72];
    __shared__ float  cs_s[32][68];
    __shared__ float  cinv_s[64];

    const int b  = blockIdx.y;
    const int m0 = blockIdx.x * 64;
    const int t  = blockIdx.x >> 1;
    const int tid = threadIdx.x;
    const int wid = tid >> 5, lane = tid & 31;
    const int wc = wid & 3, wm = wid >> 2;

    const __half* xv = XVH + (size_t)b * CC * NN;
    const __half* at = U + (size_t)b * NN * NN;
    const __half* fscale = g_rowscale + ((size_t)t * BB + b) * NN;

    float acc[2][4][4];
#pragma unroll
    for (int i = 0; i < 2; i++)
#pragma unroll
        for (int j = 0; j < 4; j++)
#pragma unroll
            for (int k = 0; k < 4; k++) acc[i][j][k] = 0.f;

    float2 cs2[4];
#pragma unroll
    for (int j = 0; j < 4; j++) cs2[j] = make_float2(0.f, 0.f);

    const int lrow = (lane & 7) + ((lane >> 3) & 1) * 8;
    const int lsel = lane >> 4;
    const int g = lane >> 3;

    for (int k0 = 0; k0 < NN; k0 += 64) {
#pragma unroll
        for (int u = 0; u < 4; u++) {
            int idx = tid + u * 256;
            int r = idx >> 3, s = idx & 7;
            *(uint4*)&XVs[r][s * 8] = *(const uint4*)&xv[(size_t)r * NN + k0 + s * 8];
        }
#pragma unroll
        for (int u = 0; u < 2; u++) {
            int idx = tid + u * 256;
            int r = idx >> 3, s = idx & 7;
            uint4 raw = *(const uint4*)&at[(size_t)(k0 + r) * NN + m0 + s * 8];
            __half2 f2 = __half2half2(fscale[k0 + r]);
            const __half2* hp = (const __half2*)&raw;
            __half2 outh[4];
#pragma unroll
            for (int j = 0; j < 4; j++) {
                __half2 prod = __hmul2(hp[j], f2);
                outh[j] = prod;
                float2 v = __half22float2(prod);
                cs2[j].x += v.x; cs2[j].y += v.y;
            }
            *(uint4*)&As[r][s * 8] = *(const uint4*)&outh[0];
        }
        __syncthreads();

#pragma unroll
        for (int kk = 0; kk < 4; kk++) {
            unsigned a[2][4];
#pragma unroll
            for (int ci = 0; ci < 2; ci++)
                ldsm_x4(a[ci][0], a[ci][1], a[ci][2], a[ci][3],
                        &XVs[wc * 32 + ci * 16 + lrow][kk * 16 + lsel * 8]);
            unsigned bf[4][2];
#pragma unroll
            for (int h = 0; h < 2; h++) {
                unsigned t0, t1, t2, t3;
                ldsm_x4_t(t0, t1, t2, t3,
                          &As[kk * 16 + (g & 1) * 8 + (lane & 7)][wm * 32 + h * 16 + (g >> 1) * 8]);
                bf[h * 2 + 0][0] = t0; bf[h * 2 + 0][1] = t1;
                bf[h * 2 + 1][0] = t2; bf[h * 2 + 1][1] = t3;
            }
#pragma unroll
            for (int ci = 0; ci < 2; ci++)
#pragma unroll
                for (int nf = 0; nf < 4; nf++)
                    mma16816(acc[ci][nf], a[ci], bf[nf]);
        }
        __syncthreads();
    }

    {
        int gg = tid >> 3, s = tid & 7;
#pragma unroll
        for (int j = 0; j < 4; j++) {
            cs_s[gg][s * 8 + 2 * j]     = cs2[j].x;
            cs_s[gg][s * 8 + 2 * j + 1] = cs2[j].y;
        }
    }
    __syncthreads();
    if (tid < 64) {
        float tot = 0.f;
#pragma unroll
        for (int gg = 0; gg < 32; gg++) tot += cs_s[gg][tid];
        cinv_s[tid] = 1.f / (1e-9f + tot);
    }
    __syncthreads();

    const int r0l = lane >> 2, c0l = (lane & 3) * 2;
#pragma unroll
    for (int ci = 0; ci < 2; ci++) {
#pragma unroll
        for (int nf = 0; nf < 4; nf++) {
            int c = wc * 32 + ci * 16 + r0l;
            int mm = wm * 32 + nf * 8 + c0l;
            float2 cv = *(const float2*)&cinv_s[mm];
            float2 lo = make_float2(acc[ci][nf][0] * cv.x, acc[ci][nf][1] * cv.y);
            *(float2*)&XR[((size_t)b * CC + c) * NN + m0 + mm] = lo;
            float2 hi = make_float2(acc[ci][nf][2] * cv.x, acc[ci][nf][3] * cv.y);
            *(float2*)&XR[((size_t)b * CC + c + 8) * NN + m0 + mm] = hi;
        }
    }
}

// ---------------- BN finalize from gemm128 partials -----------------------------
__global__ void bn_finalize_kernel(const float* __restrict__ gam, const float* __restrict__ bet)
{
    const int c = threadIdx.x;
    float ts = 0.f, t2 = 0.f;
    for (int i = 0; i < 32; i++)
#pragma unroll
        for (int b = 0; b < BB; b++) {
            ts += g_bnpS[i][b][c];
            t2 += g_bnpQ[i][b][c];
        }
    const float invN = 1.f / (float)(BB * NN);
    float mean = ts * invN;
    float var  = t2 * invN - mean * mean;
    float sc = gam[c] * rsqrtf(var + 1e-5f);
    g_scale[c] = sc;
    g_shift[c] = bet[c] - mean * sc;
}

// ---------------- BN apply (+relu) [+residual into h and output slab] -----------
__global__ __launch_bounds__(256) void bn_apply_kernel(
    const float* __restrict__ Y, float* __restrict__ H,
    float* __restrict__ OUT, int layer)
{
    size_t f = ((size_t)blockIdx.x * 256 + threadIdx.x) * 4;
    int n = (int)(f % NN);
    int c = (int)((f / NN) % CC);
    int b = (int)(f / ((size_t)NN * CC));
    float sc = g_scale[c], sh = g_shift[c];
    float4 y = *(const float4*)&Y[f];
    float4 r;
    r.x = fmaxf(fmaf(y.x, sc, sh), 0.f);
    r.y = fmaxf(fmaf(y.y, sc, sh), 0.f);
    r.z = fmaxf(fmaf(y.z, sc, sh), 0.f);
    r.w = fmaxf(fmaf(y.w, sc, sh), 0.f);
    if (OUT) {
        float4 h = *(const float4*)&H[f];
        r.x += h.x; r.y += h.y; r.z += h.z; r.w += h.w;
        *(float4*)&H[f] = r;
        *(float4*)&OUT[(((size_t)b * 4 * CC) + (size_t)layer * CC + c) * NN + n] = r;
    } else {
        *(float4*)&H[f] = r;
    }
}

// ---------------- launch ---------------------------------------------------------
extern "C" void kernel_launch(void* const* d_in, const int* in_sizes, int n_in,
                              void* d_out, int out_size)
{
    const float* x    = (const float*)d_in[0];
    const int*   mask = (const int*)  d_in[1];
    const float* w1   = (const float*)d_in[2];
    const float* g1   = (const float*)d_in[3];
    const float* b1   = (const float*)d_in[4];
    const float* w2   = (const float*)d_in[5];
    const float* g2   = (const float*)d_in[6];
    const float* b2   = (const float*)d_in[7];
    const float* wqk  = (const float*)d_in[8];
    const float* wv   = (const float*)d_in[9];
    const float* bv   = (const float*)d_in[10];
    const float* wt   = (const float*)d_in[11];
    const float* bt   = (const float*)d_in[12];
    const float* sg   = (const float*)d_in[13];
    const float* sb   = (const float*)d_in[14];
    float* out = (float*)d_out;

    float *p_h, *p_y, *p_xr;
    __half *p_xvh, *p_u, *p_qh, *p_ql, *p_qth, *p_qtl;
    cudaGetSymbolAddress((void**)&p_h,   g_h);
    cudaGetSymbolAddress((void**)&p_y,   g_y);
    cudaGetSymbolAddress((void**)&p_xvh, g_xvh);
    cudaGetSymbolAddress((void**)&p_xr,  g_xr);
    cudaGetSymbolAddress((void**)&p_u,   g_u);
    cudaGetSymbolAddress((void**)&p_qh,  g_qh);
    cudaGetSymbolAddress((void**)&p_ql,  g_ql);
    cudaGetSymbolAddress((void**)&p_qth, g_qth);
    cudaGetSymbolAddress((void**)&p_qtl, g_qtl);

    const dim3 blk256(256);
    const dim3 grid_g128(NN / 128, BB);
    const dim3 grid_qk(NN / 128, 1, BB);
    const dim3 grid_es(NN / 128, NN / 64, BB);
    const dim3 grid_rs(NN / 256, BB);
    const dim3 grid_ap(NN / 64, BB);
    const dim3 grid_ba((unsigned)(((size_t)BB * CC * NN / 4) / 256));

    // head: two conv+BN+relu
    gemm128<<<grid_g128, blk256>>>(w1, x, nullptr, nullptr, p_y, nullptr);
    bn_finalize_kernel<<<1, CC>>>(g1, b1);
    bn_apply_kernel<<<grid_ba, blk256>>>(p_y, p_h, nullptr, 0);

    gemm128<<<grid_g128, blk256>>>(w2, p_h, nullptr, nullptr, p_y, nullptr);
    bn_finalize_kernel<<<1, CC>>>(g2, b2);
    bn_apply_kernel<<<grid_ba, blk256>>>(p_y, p_h, nullptr, 0);

    // 4 offset-attention layers
    for (int i = 0; i < 4; i++) {
        gemm_qk<<<grid_qk, blk256>>>(wqk + (size_t)i * 32 * CC, p_h, p_qh, p_ql, p_qth, p_qtl);
        energy_softmax<<<grid_es, blk256>>>(p_qh, p_ql, p_qth, p_qtl, mask, p_u);
        rowscale_kernel<<<grid_rs, blk256>>>();
        gemm128<<<grid_g128, blk256>>>(wv + (size_t)i * CC * CC, p_h, nullptr, bv + (size_t)i * CC,
                                       nullptr, p_xvh);
        apply_hmma<<<grid_ap, blk256>>>(p_xvh, p_u, p_xr);
        gemm128<<<grid_g128, blk256>>>(wt + (size_t)i * CC * CC, p_h, p_xr, bt + (size_t)i * CC,
                                       p_y, nullptr);
        bn_finalize_kernel<<<1, CC>>>(sg + (size_t)i * CC, sb + (size_t)i * CC);
        bn_apply_kernel<<<grid_ba, blk256>>>(p_y, p_h, out, i);
    }
}

// round 9
// speedup vs baseline: 1.3992x; 1.0079x over previous
#include <cuda_runtime.h>
#include <cuda_fp16.h>
#include <cstdint>
#include <cstddef>

#define NN 4096
#define CC 128
#define BB 4
#define NEGV (-9e15f)
#define LOG2E 1.4426950408889634f
#define FSCALE 256.0f

typedef unsigned long long ull;

// ---------------- scratch (device globals: no allocation allowed) -----------
__device__ float  g_h[(size_t)BB * CC * NN];                 // 8 MB
__device__ float  g_y[(size_t)BB * CC * NN];                 // 8 MB
__device__ __half g_qh[(size_t)BB * 32 * NN];                // 1 MB
__device__ __half g_ql[(size_t)BB * 32 * NN];                // 1 MB
__device__ __half g_qth[(size_t)BB * NN * 32];               // 1 MB
__device__ __half g_qtl[(size_t)BB * NN * 32];               // 1 MB
__device__ __half g_xvh[(size_t)BB * CC * NN];               // 4 MB
__device__ float  g_xr[(size_t)BB * CC * NN];                // 8 MB
__device__ __half g_u[(size_t)BB * NN * NN];                 // 128 MB
__device__ float  g_tmax[(size_t)32 * BB * NN];
__device__ float  g_tsum[(size_t)32 * BB * NN];
__device__ __half g_rowscale[(size_t)32 * BB * NN];
__device__ float  g_scale[CC];
__device__ float  g_shift[CC];
__device__ float  g_bnpS[32][BB][CC];
__device__ float  g_bnpQ[32][BB][CC];

// ---------------- helpers ----------------------------------------------------
__device__ __forceinline__ void fma2(ull& acc, ull a, ull b) {
    asm("fma.rn.f32x2 %0, %1, %2, %0;" : "+l"(acc) : "l"(a), "l"(b));
}
__device__ __forceinline__ ull pack2(float v) {
    ull r;
    unsigned u = __float_as_uint(v);
    asm("mov.b64 %0, {%1, %1};" : "=l"(r) : "r"(u));
    return r;
}
__device__ __forceinline__ float2 unpack2(ull v) {
    unsigned lo, hi;
    asm("mov.b64 {%0, %1}, %2;" : "=r"(lo), "=r"(hi) : "l"(v));
    return make_float2(__uint_as_float(lo), __uint_as_float(hi));
}
__device__ __forceinline__ __half2 h2_ex2(__half2 x) {
    unsigned xi = *(unsigned*)&x;
    unsigned ri;
    asm("ex2.approx.f16x2 %0, %1;" : "=r"(ri) : "r"(xi));
    return *(__half2*)&ri;
}

// ---------------- HMMA helpers -------------------------------------------------
__device__ __forceinline__ void ldsm_x4(unsigned& r0, unsigned& r1, unsigned& r2, unsigned& r3,
                                        const void* p) {
    unsigned addr = (unsigned)__cvta_generic_to_shared(p);
    asm volatile("ldmatrix.sync.aligned.m8n8.x4.shared.b16 {%0,%1,%2,%3}, [%4];"
        : "=r"(r0), "=r"(r1), "=r"(r2), "=r"(r3) : "r"(addr));
}
__device__ __forceinline__ void ldsm_x4_t(unsigned& r0, unsigned& r1, unsigned& r2, unsigned& r3,
                                          const void* p) {
    unsigned addr = (unsigned)__cvta_generic_to_shared(p);
    asm volatile("ldmatrix.sync.aligned.m8n8.x4.trans.shared.b16 {%0,%1,%2,%3}, [%4];"
        : "=r"(r0), "=r"(r1), "=r"(r2), "=r"(r3) : "r"(addr));
}
__device__ __forceinline__ void mma16816(float d[4], const unsigned a[4], const unsigned b[2]) {
    asm volatile("mma.sync.aligned.m16n8k16.row.col.f32.f16.f16.f32 "
        "{%0,%1,%2,%3}, {%4,%5,%6,%7}, {%8,%9}, {%0,%1,%2,%3};"
        : "+f"(d[0]), "+f"(d[1]), "+f"(d[2]), "+f"(d[3])
        : "r"(a[0]), "r"(a[1]), "r"(a[2]), "r"(a[3]), "r"(b[0]), "r"(b[1]));
}

// ---------------- gemm_qk: q = Wqk (32xC) * X; FMA2; fp16 hi/lo + transposed ---
// tile 32o x 64n, 256 threads, per-thread 2o x 4n. grid (NN/64, 1, BB).
__global__ __launch_bounds__(256, 3) void gemm_qk(
    const float* __restrict__ W, const float* __restrict__ X,
    __half* __restrict__ QH, __half* __restrict__ QL,
    __half* __restrict__ QTH, __half* __restrict__ QTL)
{
    __shared__ float  Ws[CC][36];    // [c][o]
    __shared__ double Xd[64][34];    // [c_local][n-pair]

    const int b  = blockIdx.z;
    const int n0 = blockIdx.x * 64;
    const int tid = threadIdx.x;
    const int to = tid >> 4;         // 16 groups x 2o
    const int tp = tid & 15;         // 16 groups, pairs tp & tp+16

    for (int idx = tid; idx < 32 * CC; idx += 256) {
        int o = idx / CC, c = idx % CC;
        Ws[c][o] = W[(size_t)o * CC + c];
    }

    const float* x1 = X + (size_t)b * CC * NN;

    ull acc[2][2];
    acc[0][0] = acc[0][1] = acc[1][0] = acc[1][1] = 0ull;

    for (int c0 = 0; c0 < CC; c0 += 64) {
        __syncthreads();
#pragma unroll
        for (int t = 0; t < 4; t++) {
            int idx = tid + t * 256;
            int c = idx >> 4, q = idx & 15;
            float4 v = *(const float4*)&x1[(size_t)(c0 + c) * NN + n0 + q * 4];
            *(double2*)&Xd[c][q * 2] = *(const double2*)&v;
        }
        __syncthreads();
#pragma unroll 8
        for (int k = 0; k < 64; k++) {
            float2 w2 = *(const float2*)&Ws[c0 + k][to * 2];
            ull xc0 = pack2(w2.x), xc1 = pack2(w2.y);
            ull a0 = *(const ull*)&Xd[k][tp];
            ull a1 = *(const ull*)&Xd[k][tp + 16];
            fma2(acc[0][0], xc0, a0); fma2(acc[0][1], xc0, a1);
            fma2(acc[1][0], xc1, a0); fma2(acc[1][1], xc1, a1);
        }
    }

    __half h[2][2][2], l[2][2][2];   // [i][j][xy]
#pragma unroll
    for (int i = 0; i < 2; i++)
#pragma unroll
        for (int j = 0; j < 2; j++) {
            float2 v = unpack2(acc[i][j]);
            h[i][j][0] = __float2half_rn(v.x);
            l[i][j][0] = __float2half_rn(v.x - __half2float(h[i][j][0]));
            h[i][j][1] = __float2half_rn(v.y);
            l[i][j][1] = __float2half_rn(v.y - __half2float(h[i][j][1]));
        }

    // normal layout [o][n]
#pragma unroll
    for (int i = 0; i < 2; i++) {
        int o = to * 2 + i;
#pragma unroll
        for (int j = 0; j < 2; j++) {
            size_t off = ((size_t)b * 32 + o) * NN + n0 + 2 * (tp + 16 * j);
            *(__half2*)&QH[off] = __halves2half2(h[i][j][0], h[i][j][1]);
            *(__half2*)&QL[off] = __halves2half2(l[i][j][0], l[i][j][1]);
        }
    }
    // transposed layout [n][o]
#pragma unroll
    for (int j = 0; j < 2; j++)
#pragma unroll
        for (int xy = 0; xy < 2; xy++) {
            int n = n0 + 2 * (tp + 16 * j) + xy;
            size_t off = ((size_t)b * NN + n) * 32 + to * 2;
            *(__half2*)&QTH[off] = __halves2half2(h[0][j][xy], h[1][j][xy]);
            *(__half2*)&QTL[off] = __halves2half2(l[0][j][xy], l[1][j][xy]);
        }
}

// ---------------- gemm128: tile 64o x 128n, grid (NN/128, 2, BB) ---------------
// Y[b,o,n] = sum_c W[o,c]*(X1-X2)[b,c,n] + bias; fused BN partials on fp32 path.
__global__ __launch_bounds__(256, 2) void gemm128(
    const float* __restrict__ W, const float* __restrict__ X1,
    const float* __restrict__ X2, const float* __restrict__ bias,
    float* __restrict__ Y, __half* __restrict__ Yh)
{
    __shared__ float  Ws[32][68];    // [c_local][o 64]
    __shared__ double Xd[32][66];    // [c_local][n-pair]

    const int b  = blockIdx.z;
    const int o0 = blockIdx.y * 64;
    const int nb = blockIdx.x;
    const int n0 = nb * 128;
    const int tid = threadIdx.x;
    const int tp = tid & 15;
    const int tc = tid >> 4;         // 16 groups x 4o

    const float* x1 = X1 + (size_t)b * CC * NN;
    const float* x2 = X2 ? X2 + (size_t)b * CC * NN : nullptr;

    ull acc[4][4];
#pragma unroll
    for (int i = 0; i < 4; i++)
#pragma unroll
        for (int j = 0; j < 4; j++) acc[i][j] = 0ull;

    const int wo = tid & 63, wh = tid >> 6;   // W fill: o row, c-octet

    for (int c0 = 0; c0 < CC; c0 += 32) {
        {
            const float* wsrc = W + (size_t)(o0 + wo) * CC + c0 + wh * 8;
            float4 w0 = *(const float4*)&wsrc[0];
            float4 w1 = *(const float4*)&wsrc[4];
            Ws[wh * 8 + 0][wo] = w0.x; Ws[wh * 8 + 1][wo] = w0.y;
            Ws[wh * 8 + 2][wo] = w0.z; Ws[wh * 8 + 3][wo] = w0.w;
            Ws[wh * 8 + 4][wo] = w1.x; Ws[wh * 8 + 5][wo] = w1.y;
            Ws[wh * 8 + 6][wo] = w1.z; Ws[wh * 8 + 7][wo] = w1.w;
        }
#pragma unroll
        for (int t = 0; t < 4; t++) {
            int idx = tid + t * 256;
            int c = idx >> 5, q = idx & 31;
            float4 v = *(const float4*)&x1[(size_t)(c0 + c) * NN + n0 + q * 4];
            if (x2) {
                float4 w = *(const float4*)&x2[(size_t)(c0 + c) * NN + n0 + q * 4];
                v.x -= w.x; v.y -= w.y; v.z -= w.z; v.w -= w.w;
            }
            *(double2*)&Xd[c][q * 2] = *(const double2*)&v;
        }
        __syncthreads();
#pragma unroll
        for (int k = 0; k < 32; k++) {
            float4 xa = *(const float4*)&Ws[k][tc * 4];
            ull xc[4];
            xc[0] = pack2(xa.x); xc[1] = pack2(xa.y);
            xc[2] = pack2(xa.z); xc[3] = pack2(xa.w);
            ull af[4];
#pragma unroll
            for (int j = 0; j < 4; j++) af[j] = *(const ull*)&Xd[k][tp + 16 * j];
#pragma unroll
            for (int i = 0; i < 4; i++)
#pragma unroll
                for (int j = 0; j < 4; j++) fma2(acc[i][j], xc[i], af[j]);
        }
        __syncthreads();
    }

    float s_[4], q_[4];
#pragma unroll
    for (int i = 0; i < 4; i++) { s_[i] = 0.f; q_[i] = 0.f; }

#pragma unroll
    for (int i = 0; i < 4; i++) {
        int o = o0 + tc * 4 + i;
        float bi = bias ? bias[o] : 0.f;
#pragma unroll
        for (int j = 0; j < 4; j++) {
            float2 r = unpack2(acc[i][j]);
            r.x += bi; r.y += bi;
            size_t off = ((size_t)b * CC + o) * NN + n0 + 2 * (tp + 16 * j);
            if (Yh) {
                *(__half2*)&Yh[off] = __floats2half2_rn(r.x, r.y);
            } else {
                *(float2*)&Y[off] = r;
                s_[i] += r.x + r.y;
                q_[i] += r.x * r.x + r.y * r.y;
            }
        }
    }

    if (!Yh) {
#pragma unroll
        for (int i = 0; i < 4; i++) {
#pragma unroll
            for (int off = 8; off > 0; off >>= 1) {
                s_[i] += __shfl_xor_sync(0xffffffffu, s_[i], off);
                q_[i] += __shfl_xor_sync(0xffffffffu, q_[i], off);
            }
        }
        if (tp == 0) {
#pragma unroll
            for (int i = 0; i < 4; i++) {
                g_bnpS[nb][b][o0 + tc * 4 + i] = s_[i];
                g_bnpQ[nb][b][o0 + tc * 4 + i] = q_[i];
            }
        }
    }
}

// ---------------- fused energy + tile softmax (f16x2 ex2) ----------------------
__global__ __launch_bounds__(256, 2) void energy_softmax(
    const __half* __restrict__ QH, const __half* __restrict__ QL,
    const __half* __restrict__ QTH, const __half* __restrict__ QTL,
    const int* __restrict__ mask, __half* __restrict__ U)
{
    __shared__ __half Ah[64][40];
    __shared__ __half Al[64][40];
    __shared__ __half Bh[32][136];
    __shared__ __half Bl[32][136];
    __shared__ __half Us[64][136];
    __shared__ float  redu[64][4];
    __shared__ float  rowmax_s[64];
    __shared__ int    cms[128];
    __shared__ int    rms[64];

    const int b  = blockIdx.z;
    const int n0 = blockIdx.y * 64;
    const int m0 = blockIdx.x * 128;
    const int mt = blockIdx.x;
    const int tid = threadIdx.x;
    const int wid = tid >> 5, lane = tid & 31;
    const int wn = wid & 1, wm = wid >> 1;

    {
        int r = tid >> 2, s = tid & 3;
        size_t off = ((size_t)b * NN + n0 + r) * 32 + s * 8;
        *(uint4*)&Ah[r][s * 8] = *(const uint4*)&QTH[off];
        *(uint4*)&Al[r][s * 8] = *(const uint4*)&QTL[off];
    }
#pragma unroll
    for (int u = 0; u < 2; u++) {
        int idx = tid + u * 256;
        int r = idx >> 4, s = idx & 15;
        size_t off = ((size_t)b * 32 + r) * NN + m0 + s * 8;
        *(uint4*)&Bh[r][s * 8] = *(const uint4*)&QH[off];
        *(uint4*)&Bl[r][s * 8] = *(const uint4*)&QL[off];
    }
    if (tid < 128) cms[tid] = mask[(size_t)b * NN + m0 + tid];
    if (tid < 64)  rms[tid] = mask[(size_t)b * NN + n0 + tid];
    __syncthreads();

    float acc[2][4][4];
#pragma unroll
    for (int i = 0; i < 2; i++)
#pragma unroll
        for (int j = 0; j < 4; j++)
#pragma unroll
            for (int k = 0; k < 4; k++) acc[i][j][k] = 0.f;

    const int lrow = (lane & 7) + ((lane >> 3) & 1) * 8;
    const int lsel = lane >> 4;
    const int g = lane >> 3;
    const int r0l = lane >> 2, c0l = (lane & 3) * 2;

#pragma unroll
    for (int kk = 0; kk < 2; kk++) {
        unsigned ah[2][4], al[2][4];
#pragma unroll
        for (int ci = 0; ci < 2; ci++) {
            ldsm_x4(ah[ci][0], ah[ci][1], ah[ci][2], ah[ci][3],
                    &Ah[wn * 32 + ci * 16 + lrow][kk * 16 + lsel * 8]);
            ldsm_x4(al[ci][0], al[ci][1], al[ci][2], al[ci][3],
                    &Al[wn * 32 + ci * 16 + lrow][kk * 16 + lsel * 8]);
        }
        unsigned bh[4][2], bl[4][2];
#pragma unroll
        for (int h = 0; h < 2; h++) {
            unsigned t0, t1, t2, t3;
            ldsm_x4_t(t0, t1, t2, t3,
                      &Bh[kk * 16 + (g & 1) * 8 + (lane & 7)][wm * 32 + h * 16 + (g >> 1) * 8]);
            bh[h * 2 + 0][0] = t0; bh[h * 2 + 0][1] = t1;
            bh[h * 2 + 1][0] = t2; bh[h * 2 + 1][1] = t3;
            ldsm_x4_t(t0, t1, t2, t3,
                      &Bl[kk * 16 + (g & 1) * 8 + (lane & 7)][wm * 32 + h * 16 + (g >> 1) * 8]);
            bl[h * 2 + 0][0] = t0; bl[h * 2 + 0][1] = t1;
            bl[h * 2 + 1][0] = t2; bl[h * 2 + 1][1] = t3;
        }
#pragma unroll
        for (int ci = 0; ci < 2; ci++)
#pragma unroll
            for (int nf = 0; nf < 4; nf++) {
                mma16816(acc[ci][nf], ah[ci], bh[nf]);
                mma16816(acc[ci][nf], ah[ci], bl[nf]);
                mma16816(acc[ci][nf], al[ci], bh[nf]);
            }
    }

    float vmax[2][2];
    vmax[0][0] = NEGV; vmax[0][1] = NEGV; vmax[1][0] = NEGV; vmax[1][1] = NEGV;
#pragma unroll
    for (int ci = 0; ci < 2; ci++)
#pragma unroll
        for (int nf = 0; nf < 4; nf++) {
            int mm = wm * 32 + nf * 8 + c0l;
            int cm0 = cms[mm], cm1 = cms[mm + 1];
#pragma unroll
            for (int h = 0; h < 2; h++) {
                int rm = rms[wn * 32 + ci * 16 + h * 8 + r0l];
                float v0 = (rm && cm0) ? acc[ci][nf][h * 2 + 0] : NEGV;
                float v1 = (rm && cm1) ? acc[ci][nf][h * 2 + 1] : NEGV;
                acc[ci][nf][h * 2 + 0] = v0;
                acc[ci][nf][h * 2 + 1] = v1;
                vmax[ci][h] = fmaxf(vmax[ci][h], fmaxf(v0, v1));
            }
        }
#pragma unroll
    for (int ci = 0; ci < 2; ci++)
#pragma unroll
        for (int h = 0; h < 2; h++) {
            float v = vmax[ci][h];
            v = fmaxf(v, __shfl_xor_sync(0xffffffffu, v, 1));
            v = fmaxf(v, __shfl_xor_sync(0xffffffffu, v, 2));
            vmax[ci][h] = v;
        }
    if ((lane & 3) == 0) {
#pragma unroll
        for (int ci = 0; ci < 2; ci++)
#pragma unroll
            for (int h = 0; h < 2; h++)
                redu[wn * 32 + ci * 16 + h * 8 + r0l][wm] = vmax[ci][h];
    }
    __syncthreads();
    if (tid < 64) {
        float v = fmaxf(fmaxf(redu[tid][0], redu[tid][1]),
                        fmaxf(redu[tid][2], redu[tid][3]));
        rowmax_s[tid] = v;
        g_tmax[((size_t)mt * BB + b) * NN + n0 + tid] = v;
    }
    __syncthreads();

    float mx_[2][2];
#pragma unroll
    for (int ci = 0; ci < 2; ci++)
#pragma unroll
        for (int h = 0; h < 2; h++)
            mx_[ci][h] = rowmax_s[wn * 32 + ci * 16 + h * 8 + r0l];

    float rsum[2][2] = {{0.f, 0.f}, {0.f, 0.f}};
#pragma unroll
    for (int ci = 0; ci < 2; ci++)
#pragma unroll
        for (int nf = 0; nf < 4; nf++) {
            int mm = wm * 32 + nf * 8 + c0l;
#pragma unroll
            for (int h = 0; h < 2; h++) {
                float x0 = (acc[ci][nf][h * 2 + 0] - mx_[ci][h]) * LOG2E;
                float x1 = (acc[ci][nf][h * 2 + 1] - mx_[ci][h]) * LOG2E;
                __half2 u2 = h2_ex2(__floats2half2_rn(x0, x1));
                int row = wn * 32 + ci * 16 + h * 8 + r0l;
                *(__half2*)&Us[row][mm] = u2;
                float2 uf = __half22float2(u2);
                rsum[ci][h] += uf.x + uf.y;
            }
        }
#pragma unroll
    for (int ci = 0; ci < 2; ci++)
#pragma unroll
        for (int h = 0; h < 2; h++) {
            float v = rsum[ci][h];
            v += __shfl_xor_sync(0xffffffffu, v, 1);
            v += __shfl_xor_sync(0xffffffffu, v, 2);
            rsum[ci][h] = v;
        }
    if ((lane & 3) == 0) {
#pragma unroll
        for (int ci = 0; ci < 2; ci++)
#pragma unroll
            for (int h = 0; h < 2; h++)
                redu[wn * 32 + ci * 16 + h * 8 + r0l][wm] = rsum[ci][h];
    }
    __syncthreads();
    if (tid < 64) {
        float s = (redu[tid][0] + redu[tid][1]) + (redu[tid][2] + redu[tid][3]);
        g_tsum[((size_t)mt * BB + b) * NN + n0 + tid] = s;
    }
#pragma unroll
    for (int u = 0; u < 4; u++) {
        int idx = tid + u * 256;
        int r = idx >> 4, s = idx & 15;
        *(uint4*)&U[((size_t)b * NN + n0 + r) * NN + m0 + s * 8] = *(uint4*)&Us[r][s * 8];
    }
}

// ---------------- rowscale -------------------------------------------------------
__global__ __launch_bounds__(256) void rowscale_kernel()
{
    const int b = blockIdx.y;
    const int n = blockIdx.x * 256 + threadIdx.x;
    float mx[32];
    float m_row;
#pragma unroll
    for (int t = 0; t < 32; t++) {
        mx[t] = g_tmax[((size_t)t * BB + b) * NN + n];
        m_row = (t == 0) ? mx[0] : fmaxf(m_row, mx[t]);
    }
    float s = 0.f;
    float ex[32];
#pragma unroll
    for (int t = 0; t < 32; t++) {
        ex[t] = __expf(mx[t] - m_row);
        s += ex[t] * g_tsum[((size_t)t * BB + b) * NN + n];
    }
    float inv = FSCALE / s;
#pragma unroll
    for (int t = 0; t < 32; t++)
        g_rowscale[((size_t)t * BB + b) * NN + n] = __float2half_rn(ex[t] * inv);
}

// ---------------- attn apply via HMMA ------------------------------------------
__global__ __launch_bounds__(256, 2) void apply_hmma(
    const __half* __restrict__ XVH, const __half* __restrict__ U,
    float* __restrict__ XR)
{
    __shared__ __half XVs[128][72];
    __shared__ __half As[64][72];
    __shared__ float  cs_s[32][68];
    __shared__ float  cinv_s[64];

    const int b  = blockIdx.y;
    const int m0 = blockIdx.x * 64;
    const int t  = blockIdx.x >> 1;
    const int tid = threadIdx.x;
    const int wid = tid >> 5, lane = tid & 31;
    const int wc = wid & 3, wm = wid >> 2;

    const __half* xv = XVH + (size_t)b * CC * NN;
    const __half* at = U + (size_t)b * NN * NN;
    const __half* fscale = g_rowscale + ((size_t)t * BB + b) * NN;

    float acc[2][4][4];
#pragma unroll
    for (int i = 0; i < 2; i++)
#pragma unroll
        for (int j = 0; j < 4; j++)
#pragma unroll
            for (int k = 0; k < 4; k++) acc[i][j][k] = 0.f;

    float2 cs2[4];
#pragma unroll
    for (int j = 0; j < 4; j++) cs2[j] = make_float2(0.f, 0.f);

    const int lrow = (lane & 7) + ((lane >> 3) & 1) * 8;
    const int lsel = lane >> 4;
    const int g = lane >> 3;

    for (int k0 = 0; k0 < NN; k0 += 64) {
#pragma unroll
        for (int u = 0; u < 4; u++) {
            int idx = tid + u * 256;
            int r = idx >> 3, s = idx & 7;
            *(uint4*)&XVs[r][s * 8] = *(const uint4*)&xv[(size_t)r * NN + k0 + s * 8];
        }
#pragma unroll
        for (int u = 0; u < 2; u++) {
            int idx = tid + u * 256;
            int r = idx >> 3, s = idx & 7;
            uint4 raw = *(const uint4*)&at[(size_t)(k0 + r) * NN + m0 + s * 8];
            __half2 f2 = __half2half2(fscale[k0 + r]);
            const __half2* hp = (const __half2*)&raw;
            __half2 outh[4];
#pragma unroll
            for (int j = 0; j < 4; j++) {
                __half2 prod = __hmul2(hp[j], f2);
                outh[j] = prod;
                float2 v = __half22float2(prod);
                cs2[j].x += v.x; cs2[j].y += v.y;
            }
            *(uint4*)&As[r][s * 8] = *(const uint4*)&outh[0];
        }
        __syncthreads();

#pragma unroll
        for (int kk = 0; kk < 4; kk++) {
            unsigned a[2][4];
#pragma unroll
            for (int ci = 0; ci < 2; ci++)
                ldsm_x4(a[ci][0], a[ci][1], a[ci][2], a[ci][3],
                        &XVs[wc * 32 + ci * 16 + lrow][kk * 16 + lsel * 8]);
            unsigned bf[4][2];
#pragma unroll
            for (int h = 0; h < 2; h++) {
                unsigned t0, t1, t2, t3;
                ldsm_x4_t(t0, t1, t2, t3,
                          &As[kk * 16 + (g & 1) * 8 + (lane & 7)][wm * 32 + h * 16 + (g >> 1) * 8]);
                bf[h * 2 + 0][0] = t0; bf[h * 2 + 0][1] = t1;
                bf[h * 2 + 1][0] = t2; bf[h * 2 + 1][1] = t3;
            }
#pragma unroll
            for (int ci = 0; ci < 2; ci++)
#pragma unroll
                for (int nf = 0; nf < 4; nf++)
                    mma16816(acc[ci][nf], a[ci], bf[nf]);
        }
        __syncthreads();
    }

    {
        int gg = tid >> 3, s = tid & 7;
#pragma unroll
        for (int j = 0; j < 4; j++) {
            cs_s[gg][s * 8 + 2 * j]     = cs2[j].x;
            cs_s[gg][s * 8 + 2 * j + 1] = cs2[j].y;
        }
    }
    __syncthreads();
    if (tid < 64) {
        float tot = 0.f;
#pragma unroll
        for (int gg = 0; gg < 32; gg++) tot += cs_s[gg][tid];
        cinv_s[tid] = 1.f / (1e-9f + tot);
    }
    __syncthreads();

    const int r0l = lane >> 2, c0l = (lane & 3) * 2;
#pragma unroll
    for (int ci = 0; ci < 2; ci++) {
#pragma unroll
        for (int nf = 0; nf < 4; nf++) {
            int c = wc * 32 + ci * 16 + r0l;
            int mm = wm * 32 + nf * 8 + c0l;
            float2 cv = *(const float2*)&cinv_s[mm];
            float2 lo = make_float2(acc[ci][nf][0] * cv.x, acc[ci][nf][1] * cv.y);
            *(float2*)&XR[((size_t)b * CC + c) * NN + m0 + mm] = lo;
            float2 hi = make_float2(acc[ci][nf][2] * cv.x, acc[ci][nf][3] * cv.y);
            *(float2*)&XR[((size_t)b * CC + c + 8) * NN + m0 + mm] = hi;
        }
    }
}

// ---------------- BN finalize from gemm128 partials -----------------------------
__global__ void bn_finalize_kernel(const float* __restrict__ gam, const float* __restrict__ bet)
{
    const int c = threadIdx.x;
    float ts = 0.f, t2 = 0.f;
    for (int i = 0; i < 32; i++)
#pragma unroll
        for (int b = 0; b < BB; b++) {
            ts += g_bnpS[i][b][c];
            t2 += g_bnpQ[i][b][c];
        }
    const float invN = 1.f / (float)(BB * NN);
    float mean = ts * invN;
    float var  = t2 * invN - mean * mean;
    float sc = gam[c] * rsqrtf(var + 1e-5f);
    g_scale[c] = sc;
    g_shift[c] = bet[c] - mean * sc;
}

// ---------------- BN apply (+relu) [+residual into h and output slab] -----------
__global__ __launch_bounds__(256) void bn_apply_kernel(
    const float* __restrict__ Y, float* __restrict__ H,
    float* __restrict__ OUT, int layer)
{
    size_t f = ((size_t)blockIdx.x * 256 + threadIdx.x) * 4;
    int n = (int)(f % NN);
    int c = (int)((f / NN) % CC);
    int b = (int)(f / ((size_t)NN * CC));
    float sc = g_scale[c], sh = g_shift[c];
    float4 y = *(const float4*)&Y[f];
    float4 r;
    r.x = fmaxf(fmaf(y.x, sc, sh), 0.f);
    r.y = fmaxf(fmaf(y.y, sc, sh), 0.f);
    r.z = fmaxf(fmaf(y.z, sc, sh), 0.f);
    r.w = fmaxf(fmaf(y.w, sc, sh), 0.f);
    if (OUT) {
        float4 h = *(const float4*)&H[f];
        r.x += h.x; r.y += h.y; r.z += h.z; r.w += h.w;
        *(float4*)&H[f] = r;
        *(float4*)&OUT[(((size_t)b * 4 * CC) + (size_t)layer * CC + c) * NN + n] = r;
    } else {
        *(float4*)&H[f] = r;
    }
}

// ---------------- launch ---------------------------------------------------------
extern "C" void kernel_launch(void* const* d_in, const int* in_sizes, int n_in,
                              void* d_out, int out_size)
{
    const float* x    = (const float*)d_in[0];
    const int*   mask = (const int*)  d_in[1];
    const float* w1   = (const float*)d_in[2];
    const float* g1   = (const float*)d_in[3];
    const float* b1   = (const float*)d_in[4];
    const float* w2   = (const float*)d_in[5];
    const float* g2   = (const float*)d_in[6];
    const float* b2   = (const float*)d_in[7];
    const float* wqk  = (const float*)d_in[8];
    const float* wv   = (const float*)d_in[9];
    const float* bv   = (const float*)d_in[10];
    const float* wt   = (const float*)d_in[11];
    const float* bt   = (const float*)d_in[12];
    const float* sg   = (const float*)d_in[13];
    const float* sb   = (const float*)d_in[14];
    float* out = (float*)d_out;

    float *p_h, *p_y, *p_xr;
    __half *p_xvh, *p_u, *p_qh, *p_ql, *p_qth, *p_qtl;
    cudaGetSymbolAddress((void**)&p_h,   g_h);
    cudaGetSymbolAddress((void**)&p_y,   g_y);
    cudaGetSymbolAddress((void**)&p_xvh, g_xvh);
    cudaGetSymbolAddress((void**)&p_xr,  g_xr);
    cudaGetSymbolAddress((void**)&p_u,   g_u);
    cudaGetSymbolAddress((void**)&p_qh,  g_qh);
    cudaGetSymbolAddress((void**)&p_ql,  g_ql);
    cudaGetSymbolAddress((void**)&p_qth, g_qth);
    cudaGetSymbolAddress((void**)&p_qtl, g_qtl);

    const dim3 blk256(256);
    const dim3 grid_g128(NN / 128, 2, BB);       // 256 CTAs
    const dim3 grid_qk(NN / 64, 1, BB);          // 256 CTAs
    const dim3 grid_es(NN / 128, NN / 64, BB);
    const dim3 grid_rs(NN / 256, BB);
    const dim3 grid_ap(NN / 64, BB);
    const dim3 grid_ba((unsigned)(((size_t)BB * CC * NN / 4) / 256));

    // head: two conv+BN+relu
    gemm128<<<grid_g128, blk256>>>(w1, x, nullptr, nullptr, p_y, nullptr);
    bn_finalize_kernel<<<1, CC>>>(g1, b1);
    bn_apply_kernel<<<grid_ba, blk256>>>(p_y, p_h, nullptr, 0);

    gemm128<<<grid_g128, blk256>>>(w2, p_h, nullptr, nullptr, p_y, nullptr);
    bn_finalize_kernel<<<1, CC>>>(g2, b2);
    bn_apply_kernel<<<grid_ba, blk256>>>(p_y, p_h, nullptr, 0);

    // 4 offset-attention layers
    for (int i = 0; i < 4; i++) {
        gemm_qk<<<grid_qk, blk256>>>(wqk + (size_t)i * 32 * CC, p_h, p_qh, p_ql, p_qth, p_qtl);
        energy_softmax<<<grid_es, blk256>>>(p_qh, p_ql, p_qth, p_qtl, mask, p_u);
        rowscale_kernel<<<grid_rs, blk256>>>();
        gemm128<<<grid_g128, blk256>>>(wv + (size_t)i * CC * CC, p_h, nullptr, bv + (size_t)i * CC,
                                       nullptr, p_xvh);
        apply_hmma<<<grid_ap, blk256>>>(p_xvh, p_u, p_xr);
        gemm128<<<grid_g128, blk256>>>(wt + (size_t)i * CC * CC, p_h, p_xr, bt + (size_t)i * CC,
                                       p_y, nullptr);
        bn_finalize_kernel<<<1, CC>>>(sg + (size_t)i * CC, sb + (size_t)i * CC);
        bn_apply_kernel<<<grid_ba, blk256>>>(p_y, p_h, out, i);
    }
}